// round 9
// baseline (speedup 1.0000x reference)
#include <cuda_runtime.h>
#include <cuda_bf16.h>
#include <math.h>

typedef unsigned int u32;

#define OPACITY_TH 0.01f
#define EARLY_TERM 1e-4f

__device__ __forceinline__ u32 cvt2(float hi_f, float lo_f) {
    u32 r; asm("cvt.rn.bf16x2.f32 %0, %1, %2;" : "=r"(r) : "f"(hi_f), "f"(lo_f)); return r;
}

__device__ __forceinline__ void mma_bf16(float& d0, float& d1, float& d2, float& d3,
                                         u32 a0, u32 a1, u32 a2, u32 a3,
                                         u32 b0, u32 b1) {
    asm volatile("mma.sync.aligned.m16n8k16.row.col.f32.bf16.bf16.f32 "
        "{%0,%1,%2,%3}, {%4,%5,%6,%7}, {%8,%9}, {%0,%1,%2,%3};"
        : "+f"(d0), "+f"(d1), "+f"(d2), "+f"(d3)
        : "r"(a0), "r"(a1), "r"(a2), "r"(a3), "r"(b0), "r"(b1));
}

// ---------------- precomputed globals (prep kernel output) ----------------
__device__ __align__(16) uint4 g_Bfrag[64 * 32];
__device__ float g_ws[128];      // f_w2[k,:]·s_w
__device__ float g_hconst[64];   // f_b2 @ r_w1[:64,:] + r_b1
__device__ float g_sconst[1];    // f_b2·s_w + s_b

__global__ void prep_kernel(const float* __restrict__ f_w2, const float* __restrict__ f_b2,
                            const float* __restrict__ s_w,  const float* __restrict__ s_b,
                            const float* __restrict__ r_w1, const float* __restrict__ r_b1)
{
    int i = blockIdx.x * blockDim.x + threadIdx.x;
    if (i < 2048) {
        int fid = i >> 5, lane = i & 31;
        int nt = fid >> 3, kt = fid & 7;
        int n = nt * 8 + (lane >> 2);
        int tq = lane & 3;
        int k0 = kt * 16 + 2 * tq;
        float v[4]; float lo[4];
        #pragma unroll
        for (int e = 0; e < 4; e++) {
            int k = k0 + (e >> 1) * 8 + (e & 1);
            float s = 0.0f;
            #pragma unroll 8
            for (int t = 0; t < 64; t++) s += f_w2[k * 64 + t] * r_w1[t * 64 + n];
            __nv_bfloat16 bh = __float2bfloat16(s);
            v[e] = s;
            lo[e] = s - __bfloat162float(bh);
        }
        uint4 o;
        o.x = cvt2(v[1], v[0]);
        o.y = cvt2(v[3], v[2]);
        o.z = cvt2(lo[1], lo[0]);
        o.w = cvt2(lo[3], lo[2]);
        g_Bfrag[fid * 32 + lane] = o;
    } else if (i < 2176) {
        int k = i - 2048;
        float s = 0.0f;
        #pragma unroll 8
        for (int t = 0; t < 64; t++) s += f_w2[k * 64 + t] * s_w[t];
        g_ws[k] = s;
    } else if (i < 2240) {
        int j = i - 2176;
        float s = r_b1[j];
        #pragma unroll 8
        for (int t = 0; t < 64; t++) s += f_b2[t] * r_w1[t * 64 + j];
        g_hconst[j] = s;
    } else if (i == 2240) {
        float s = s_b[0];
        for (int t = 0; t < 64; t++) s += f_b2[t] * s_w[t];
        g_sconst[0] = s;
    }
}

// ---------------- dynamic shared layout (bytes) ----------------
#define SM_BFRAG 0        // 32KB
#define SM_W1B   32768    // [128][4] f32 2KB
#define SM_WS    34816    // 512B
#define SM_RW2   35328    // [64][4] 1KB
#define SM_SIGB  36352    // sigma_pre[256] 1KB
#define SM_RGBB  37376    // rgbRaw[256] float4 4KB
#define SM_MISC  41472
#define SMEM_BYTES 41488

__device__ __forceinline__ float tmap(float u) {
    return (u < 0.5f) ? 2.0f * u : 1.0f / (2.0f - 2.0f * u);
}

#define USTEP ((257.0f / 258.0f) / 256.0f)

__device__ __forceinline__ void ray_pos(int s, float ox, float oy, float oz,
                                        float dx, float dy, float dz,
                                        float& px, float& py, float& pz) {
    float tv = tmap((float)s * USTEP);
    px = ox + dx * tv; py = oy + dy * tv; pz = oz + dz * tv;
    float nrm = sqrtf(px * px + py * py + pz * pz);
    float cs = (nrm <= 1.0f) ? 0.5f : (2.0f - 1.0f / nrm) / nrm * 0.5f;
    px *= cs; py *= cs; pz *= cs;
}

__device__ __forceinline__ float sample_grid(const float* __restrict__ grid,
                                             float px, float py, float pz) {
    float ixf = ((px + 1.0f) * 128.0f - 1.0f) * 0.5f;
    float iyf = ((py + 1.0f) * 128.0f - 1.0f) * 0.5f;
    float izf = ((pz + 1.0f) * 128.0f - 1.0f) * 0.5f;
    float fx0 = floorf(ixf), fy0 = floorf(iyf), fz0 = floorf(izf);
    int ix0 = (int)fx0, iy0 = (int)fy0, iz0 = (int)fz0;
    float fx = ixf - fx0, fy = iyf - fy0, fz = izf - fz0;
    float occ = 0.0f;
    #pragma unroll
    for (int dzc = 0; dzc < 2; dzc++) {
        int cz = iz0 + dzc;
        if (cz < 0 || cz >= 128) continue;
        float wz = dzc ? fz : 1.0f - fz;
        #pragma unroll
        for (int dyc = 0; dyc < 2; dyc++) {
            int cy = iy0 + dyc;
            if (cy < 0 || cy >= 128) continue;
            float wy = dyc ? fy : 1.0f - fy;
            #pragma unroll
            for (int dxc = 0; dxc < 2; dxc++) {
                int cx = ix0 + dxc;
                if (cx < 0 || cx >= 128) continue;
                float wx = dxc ? fx : 1.0f - fx;
                occ += wz * wy * wx * __ldg(&grid[(cz << 14) + (cy << 7) + cx]);
            }
        }
    }
    return occ;
}

__global__ void __launch_bounds__(128, 5) nerf_render_kernel(
    const float* __restrict__ rays_o, const float* __restrict__ rays_d,
    const float* __restrict__ grid,
    const float* __restrict__ f_w1, const float* __restrict__ f_b1,
    const float* __restrict__ r_w1, const float* __restrict__ r_w2,
    const float* __restrict__ r_b2,
    float* __restrict__ out)
{
    extern __shared__ __align__(16) char smdyn[];
    __shared__ float wsumA[4], wsumB[4];
    __shared__ float wred[4][3];

    const int tid = threadIdx.x;
    const int wid = tid >> 5;
    const int lid = tid & 31;
    const int g   = lid >> 2;
    const int tq  = lid & 3;
    const int ray = blockIdx.x;

    const float ox = __ldg(&rays_o[ray * 3 + 0]);
    const float oy = __ldg(&rays_o[ray * 3 + 1]);
    const float oz = __ldg(&rays_o[ray * 3 + 2]);
    const float dx = __ldg(&rays_d[ray * 3 + 0]);
    const float dy = __ldg(&rays_d[ray * 3 + 1]);
    const float dz = __ldg(&rays_d[ray * 3 + 2]);

    // ---- EARLY: phase-B occupancy loads (hidden behind staging + phase A) ----
    bool mA, mB;
    {
        float pxA, pyA, pzA, pxB, pyB, pzB;
        ray_pos(tid, ox, oy, oz, dx, dy, dz, pxA, pyA, pzA);
        ray_pos(tid + 128, ox, oy, oz, dx, dy, dz, pxB, pyB, pzB);
        mA = sample_grid(grid, pxA, pyA, pzA) > OPACITY_TH;
        mB = sample_grid(grid, pxB, pyB, pzB) > OPACITY_TH;
    }

    // ---- staging ----
    {
        uint4* dstB = (uint4*)(smdyn + SM_BFRAG);
        #pragma unroll
        for (int i = 0; i < 16; i++) dstB[tid + 128 * i] = g_Bfrag[tid + 128 * i];
        float* dw1b = (float*)(smdyn + SM_W1B);
        for (int i = tid; i < 512; i += 128) {
            int k = i >> 2, c = i & 3;
            dw1b[i] = (c < 3) ? f_w1[c * 128 + k] : f_b1[k];
        }
        ((float*)(smdyn + SM_WS))[tid] = g_ws[tid];
        if (tid < 64) {
            float hcv = g_hconst[tid]
                      + dx * r_w1[64 * 64 + tid]
                      + dy * r_w1[65 * 64 + tid]
                      + dz * r_w1[66 * 64 + tid];
            *(float4*)(smdyn + SM_RW2 + tid * 16) =
                make_float4(r_w2[tid * 3], r_w2[tid * 3 + 1], r_w2[tid * 3 + 2], hcv);
        }
        if (tid < 3)  ((float*)(smdyn + SM_MISC))[tid] = r_b2[tid];
        if (tid == 3) ((float*)(smdyn + SM_MISC))[3] = g_sconst[0];
    }
    __syncthreads();

    const float4* w1bv = (const float4*)(smdyn + SM_W1B);
    const float*  wsf  = (const float*)(smdyn + SM_WS);
    const uint4*  bp   = (const uint4*)(smdyn + SM_BFRAG);
    const float4* qrw2 = (const float4*)(smdyn + SM_RW2);
    float*        sigb = (float*)(smdyn + SM_SIGB);
    float4*       rgbb = (float4*)(smdyn + SM_RGBB);
    const float rb0  = ((const float*)(smdyn + SM_MISC))[0];
    const float rb1  = ((const float*)(smdyn + SM_MISC))[1];
    const float rb2v = ((const float*)(smdyn + SM_MISC))[2];
    const float sconst = ((const float*)(smdyn + SM_MISC))[3];

    // ========== PHASE A: per-tile k-halved frag build + MMA + epilogue =======
    #pragma unroll
    for (int mt = 0; mt < 4; mt++) {
        const int tt = wid * 4 + mt;
        const int r0 = 16 * tt + g;
        const int r1 = r0 + 8;

        float px0, py0, pz0, px1, py1, pz1;
        ray_pos(r0, ox, oy, oz, dx, dy, dz, px0, py0, pz0);
        ray_pos(r1, ox, oy, oz, dx, dy, dz, px1, py1, pz1);

        float D0[8], D1[8], D2[8], D3[8];
        #pragma unroll
        for (int nt = 0; nt < 8; nt++) { D0[nt] = D1[nt] = D2[nt] = D3[nt] = 0.0f; }
        float sp0 = 0.0f, sp1 = 0.0f;

        #pragma unroll
        for (int half = 0; half < 2; half++) {
            // build 4 kt of A fragments (hi + lo)
            u32 ahi[4][4], alo[4][4];
            #pragma unroll
            for (int k4 = 0; k4 < 4; k4++) {
                const int kt = half * 4 + k4;
                const int k0 = kt * 16 + 2 * tq;
                float4 wa = w1bv[k0],     wb = w1bv[k0 + 1];
                float4 wc = w1bv[k0 + 8], wd = w1bv[k0 + 9];
                float h00 = fmaxf(wa.w + px0 * wa.x + py0 * wa.y + pz0 * wa.z, 0.0f);
                float h01 = fmaxf(wb.w + px0 * wb.x + py0 * wb.y + pz0 * wb.z, 0.0f);
                float h08 = fmaxf(wc.w + px0 * wc.x + py0 * wc.y + pz0 * wc.z, 0.0f);
                float h09 = fmaxf(wd.w + px0 * wd.x + py0 * wd.y + pz0 * wd.z, 0.0f);
                float h10 = fmaxf(wa.w + px1 * wa.x + py1 * wa.y + pz1 * wa.z, 0.0f);
                float h11 = fmaxf(wb.w + px1 * wb.x + py1 * wb.y + pz1 * wb.z, 0.0f);
                float h18 = fmaxf(wc.w + px1 * wc.x + py1 * wc.y + pz1 * wc.z, 0.0f);
                float h19 = fmaxf(wd.w + px1 * wd.x + py1 * wd.y + pz1 * wd.z, 0.0f);
                float2 wsa = *(const float2*)&wsf[k0];
                float2 wsb = *(const float2*)&wsf[k0 + 8];
                sp0 = fmaf(h00, wsa.x, fmaf(h01, wsa.y, fmaf(h08, wsb.x, fmaf(h09, wsb.y, sp0))));
                sp1 = fmaf(h10, wsa.x, fmaf(h11, wsa.y, fmaf(h18, wsb.x, fmaf(h19, wsb.y, sp1))));
                u32 x0 = cvt2(h01, h00);
                u32 x1 = cvt2(h11, h10);
                u32 x2 = cvt2(h09, h08);
                u32 x3 = cvt2(h19, h18);
                ahi[k4][0] = x0; ahi[k4][1] = x1; ahi[k4][2] = x2; ahi[k4][3] = x3;
                float f00 = __uint_as_float(x0 << 16), f01 = __uint_as_float(x0 & 0xFFFF0000u);
                float f10 = __uint_as_float(x1 << 16), f11 = __uint_as_float(x1 & 0xFFFF0000u);
                float f08 = __uint_as_float(x2 << 16), f09 = __uint_as_float(x2 & 0xFFFF0000u);
                float f18 = __uint_as_float(x3 << 16), f19 = __uint_as_float(x3 & 0xFFFF0000u);
                alo[k4][0] = cvt2(h01 - f01, h00 - f00);
                alo[k4][1] = cvt2(h11 - f11, h10 - f10);
                alo[k4][2] = cvt2(h09 - f09, h08 - f08);
                alo[k4][3] = cvt2(h19 - f19, h18 - f18);
            }
            // MMA this k-half into per-nt D partials
            #pragma unroll
            for (int nt = 0; nt < 8; nt++) {
                float p0 = 0.0f, p1 = 0.0f, p2 = 0.0f, p3 = 0.0f;   // hi*hi + lo*hi
                float q0 = 0.0f, q1 = 0.0f, q2 = 0.0f, q3 = 0.0f;   // hi*lo
                const uint4* bnt = bp + nt * 256 + half * 128 + lid;
                #pragma unroll
                for (int k4 = 0; k4 < 4; k4++) {
                    uint4 b = bnt[k4 * 32];
                    mma_bf16(p0, p1, p2, p3, ahi[k4][0], ahi[k4][1], ahi[k4][2], ahi[k4][3], b.x, b.y);
                    mma_bf16(q0, q1, q2, q3, ahi[k4][0], ahi[k4][1], ahi[k4][2], ahi[k4][3], b.z, b.w);
                    mma_bf16(p0, p1, p2, p3, alo[k4][0], alo[k4][1], alo[k4][2], alo[k4][3], b.x, b.y);
                }
                D0[nt] += p0 + q0; D1[nt] += p1 + q1;
                D2[nt] += p2 + q2; D3[nt] += p3 + q3;
            }
        }
        // sigma-dot quad reduce
        sp0 += __shfl_xor_sync(0xffffffffu, sp0, 1);
        sp0 += __shfl_xor_sync(0xffffffffu, sp0, 2);
        sp1 += __shfl_xor_sync(0xffffffffu, sp1, 1);
        sp1 += __shfl_xor_sync(0xffffffffu, sp1, 2);
        if (tq == 0) { sigb[r0] = sp0; sigb[r1] = sp1; }

        // epilogue fold over nt
        float a00 = 0.0f, a01 = 0.0f, a02 = 0.0f;
        float a10 = 0.0f, a11 = 0.0f, a12 = 0.0f;
        #pragma unroll
        for (int nt = 0; nt < 8; nt++) {
            const int c = nt * 8 + 2 * tq;
            float4 wA = qrw2[c], wB = qrw2[c + 1];
            float hA0 = fmaxf(D0[nt] + wA.w, 0.0f);
            float hA1 = fmaxf(D1[nt] + wB.w, 0.0f);
            float hB0 = fmaxf(D2[nt] + wA.w, 0.0f);
            float hB1 = fmaxf(D3[nt] + wB.w, 0.0f);
            a00 = fmaf(hA0, wA.x, fmaf(hA1, wB.x, a00));
            a01 = fmaf(hA0, wA.y, fmaf(hA1, wB.y, a01));
            a02 = fmaf(hA0, wA.z, fmaf(hA1, wB.z, a02));
            a10 = fmaf(hB0, wA.x, fmaf(hB1, wB.x, a10));
            a11 = fmaf(hB0, wA.y, fmaf(hB1, wB.y, a11));
            a12 = fmaf(hB0, wA.z, fmaf(hB1, wB.z, a12));
        }
        #pragma unroll
        for (int d = 1; d <= 2; d <<= 1) {
            a00 += __shfl_xor_sync(0xffffffffu, a00, d);
            a01 += __shfl_xor_sync(0xffffffffu, a01, d);
            a02 += __shfl_xor_sync(0xffffffffu, a02, d);
            a10 += __shfl_xor_sync(0xffffffffu, a10, d);
            a11 += __shfl_xor_sync(0xffffffffu, a11, d);
            a12 += __shfl_xor_sync(0xffffffffu, a12, d);
        }
        if (tq == 0) {
            rgbb[r0] = make_float4(1.0f / (1.0f + expf(-(a00 + rb0))),
                                   1.0f / (1.0f + expf(-(a01 + rb1))),
                                   1.0f / (1.0f + expf(-(a02 + rb2v))), 0.0f);
            rgbb[r1] = make_float4(1.0f / (1.0f + expf(-(a10 + rb0))),
                                   1.0f / (1.0f + expf(-(a11 + rb1))),
                                   1.0f / (1.0f + expf(-(a12 + rb2v))), 0.0f);
        }
    }
    __syncthreads();

    // ========== PHASE B: scan + weighted accumulation ========================
    float rgb0, rgb1, rgb2;
    {
        float tA  = tmap((float)tid * USTEP);
        float tA1 = tmap((float)(tid + 1) * USTEP);
        float tB  = tmap((float)(tid + 128) * USTEP);
        float tB1 = tmap((float)(tid + 129) * USTEP);
        float distA = tA1 - tA, distB = tB1 - tB;

        float preA = sigb[tid] + sconst;
        float preB = sigb[tid + 128] + sconst;
        float sigmaA = mA ? ((preA > 20.0f) ? preA : log1pf(expf(preA))) : 0.0f;
        float sigmaB = mB ? ((preB > 20.0f) ? preB : log1pf(expf(preB))) : 0.0f;

        float aA = -sigmaA * distA;
        float aB = -sigmaB * distB;
        float incA = aA, incB = aB;
        #pragma unroll
        for (int off = 1; off < 32; off <<= 1) {
            float yA = __shfl_up_sync(0xffffffffu, incA, off);
            float yB = __shfl_up_sync(0xffffffffu, incB, off);
            if (lid >= off) { incA += yA; incB += yB; }
        }
        if (lid == 31) { wsumA[wid] = incA; wsumB[wid] = incB; }
        __syncthreads();
        float offA = 0.0f, offB = 0.0f, totalA = 0.0f;
        #pragma unroll
        for (int i = 0; i < 4; i++) {
            float vA = wsumA[i];
            totalA += vA;
            if (i < wid) { offA += vA; offB += wsumB[i]; }
        }
        float exclA = offA + incA - aA;
        float exclB = totalA + offB + incB - aB;
        float transA = expf(exclA), transB = expf(exclB);
        float weightA = transA * (1.0f - expf(aA));
        float weightB = transB * (1.0f - expf(aB));
        float wA = (mA && transA > EARLY_TERM) ? weightA : 0.0f;
        float wB = (mB && transB > EARLY_TERM) ? weightB : 0.0f;

        float4 cA = rgbb[tid];
        float4 cB = rgbb[tid + 128];
        rgb0 = wA * cA.x + wB * cB.x;
        rgb1 = wA * cA.y + wB * cB.y;
        rgb2 = wA * cA.z + wB * cB.z;
    }

    // ---- deterministic block reduction ----
    #pragma unroll
    for (int off = 16; off > 0; off >>= 1) {
        rgb0 += __shfl_down_sync(0xffffffffu, rgb0, off);
        rgb1 += __shfl_down_sync(0xffffffffu, rgb1, off);
        rgb2 += __shfl_down_sync(0xffffffffu, rgb2, off);
    }
    if (lid == 0) { wred[wid][0] = rgb0; wred[wid][1] = rgb1; wred[wid][2] = rgb2; }
    __syncthreads();
    if (tid < 3) {
        float s = 0.0f;
        #pragma unroll
        for (int w = 0; w < 4; w++) s += wred[w][tid];
        out[ray * 3 + tid] = s;
    }
}

extern "C" void kernel_launch(void* const* d_in, const int* in_sizes, int n_in,
                              void* d_out, int out_size) {
    const float* rays_o = (const float*)d_in[0];
    const float* rays_d = (const float*)d_in[1];
    const float* grid   = (const float*)d_in[2];
    const float* f_w1   = (const float*)d_in[3];
    const float* f_b1   = (const float*)d_in[4];
    const float* f_w2   = (const float*)d_in[5];
    const float* f_b2   = (const float*)d_in[6];
    const float* s_w    = (const float*)d_in[7];
    const float* s_b    = (const float*)d_in[8];
    const float* r_w1   = (const float*)d_in[9];
    const float* r_b1   = (const float*)d_in[10];
    const float* r_w2   = (const float*)d_in[11];
    const float* r_b2   = (const float*)d_in[12];
    float* out = (float*)d_out;

    const int n_rays = in_sizes[0] / 3;

    prep_kernel<<<(2241 + 255) / 256, 256>>>(f_w2, f_b2, s_w, s_b, r_w1, r_b1);

    cudaFuncSetAttribute(nerf_render_kernel,
                         cudaFuncAttributeMaxDynamicSharedMemorySize, SMEM_BYTES);
    nerf_render_kernel<<<n_rays, 128, SMEM_BYTES>>>(
        rays_o, rays_d, grid, f_w1, f_b1, r_w1, r_w2, r_b2, out);
}

// round 10
// speedup vs baseline: 1.2245x; 1.2245x over previous
#include <cuda_runtime.h>
#include <cuda_fp16.h>
#include <math.h>

typedef unsigned int u32;

#define OPACITY_TH 0.01f
#define EARLY_TERM 1e-4f

// pack two floats to f16x2: low16 = f16(lo_f), high16 = f16(hi_f)
__device__ __forceinline__ u32 packh(float lo_f, float hi_f) {
    __half2 h = __halves2half2(__float2half_rn(lo_f), __float2half_rn(hi_f));
    return *reinterpret_cast<u32*>(&h);
}
__device__ __forceinline__ float2 unpackh(u32 v) {
    __half2 h = *reinterpret_cast<__half2*>(&v);
    return __half22float2(h);
}

__device__ __forceinline__ void mma_f16(float& d0, float& d1, float& d2, float& d3,
                                        u32 a0, u32 a1, u32 a2, u32 a3,
                                        u32 b0, u32 b1) {
    asm volatile("mma.sync.aligned.m16n8k16.row.col.f32.f16.f16.f32 "
        "{%0,%1,%2,%3}, {%4,%5,%6,%7}, {%8,%9}, {%0,%1,%2,%3};"
        : "+f"(d0), "+f"(d1), "+f"(d2), "+f"(d3)
        : "r"(a0), "r"(a1), "r"(a2), "r"(a3), "r"(b0), "r"(b1));
}

// ---------------- precomputed globals (prep kernel output) ----------------
// B fragments (fp16): fid = nt*8+kt, lane l: n = nt*8+(l>>2), tq=l&3, k0=kt*16+2tq
//   uint2 = { bh(k0,k0+1), bh(k0+8,k0+9) }
__device__ __align__(16) uint2 g_Bh[64 * 32];
__device__ float g_ws[128];      // f_w2[k,:]·s_w
__device__ float g_hconst[64];   // f_b2 @ r_w1[:64,:] + r_b1
__device__ float g_sconst[1];    // f_b2·s_w + s_b

__global__ void prep_kernel(const float* __restrict__ f_w2, const float* __restrict__ f_b2,
                            const float* __restrict__ s_w,  const float* __restrict__ s_b,
                            const float* __restrict__ r_w1, const float* __restrict__ r_b1)
{
    int i = blockIdx.x * blockDim.x + threadIdx.x;
    if (i < 2048) {
        int fid = i >> 5, lane = i & 31;
        int nt = fid >> 3, kt = fid & 7;
        int n = nt * 8 + (lane >> 2);
        int tq = lane & 3;
        int k0 = kt * 16 + 2 * tq;
        float v[4];
        #pragma unroll
        for (int e = 0; e < 4; e++) {
            int k = k0 + (e >> 1) * 8 + (e & 1);   // k0, k0+1, k0+8, k0+9
            float s = 0.0f;
            #pragma unroll 8
            for (int t = 0; t < 64; t++) s += f_w2[k * 64 + t] * r_w1[t * 64 + n];
            v[e] = s;
        }
        uint2 o;
        o.x = packh(v[0], v[1]);
        o.y = packh(v[2], v[3]);
        g_Bh[fid * 32 + lane] = o;
    } else if (i < 2176) {
        int k = i - 2048;
        float s = 0.0f;
        #pragma unroll 8
        for (int t = 0; t < 64; t++) s += f_w2[k * 64 + t] * s_w[t];
        g_ws[k] = s;
    } else if (i < 2240) {
        int j = i - 2176;
        float s = r_b1[j];
        #pragma unroll 8
        for (int t = 0; t < 64; t++) s += f_b2[t] * r_w1[t * 64 + j];
        g_hconst[j] = s;
    } else if (i == 2240) {
        float s = s_b[0];
        for (int t = 0; t < 64; t++) s += f_b2[t] * s_w[t];
        g_sconst[0] = s;
    }
}

// ---------------- dynamic shared layout (bytes) ----------------
#define SM_BH    0        // 16KB uint2[2048]
#define SM_W1B   16384    // [128][4] f32 2KB
#define SM_WS    18432    // 512B
#define SM_RW2   18944    // [64][4] 1KB
#define SM_SIGB  19968    // sigma_pre[256] 1KB
#define SM_RGBB  20992    // rgbRaw[256] float4 4KB
#define SM_MISC  25088    // [0..2]=r_b2, [3]=sconst
#define SMEM_BYTES 25104

__device__ __forceinline__ float tmap(float u) {
    return (u < 0.5f) ? 2.0f * u : 1.0f / (2.0f - 2.0f * u);
}

#define USTEP ((257.0f / 258.0f) / 256.0f)

__device__ __forceinline__ void ray_pos(int s, float ox, float oy, float oz,
                                        float dx, float dy, float dz,
                                        float& px, float& py, float& pz) {
    float tv = tmap((float)s * USTEP);
    px = ox + dx * tv; py = oy + dy * tv; pz = oz + dz * tv;
    float nrm = sqrtf(px * px + py * py + pz * pz);
    float cs = (nrm <= 1.0f) ? 0.5f : (2.0f - 1.0f / nrm) / nrm * 0.5f;
    px *= cs; py *= cs; pz *= cs;
}

__device__ __forceinline__ float sample_grid(const float* __restrict__ grid,
                                             float px, float py, float pz) {
    float ixf = ((px + 1.0f) * 128.0f - 1.0f) * 0.5f;
    float iyf = ((py + 1.0f) * 128.0f - 1.0f) * 0.5f;
    float izf = ((pz + 1.0f) * 128.0f - 1.0f) * 0.5f;
    float fx0 = floorf(ixf), fy0 = floorf(iyf), fz0 = floorf(izf);
    int ix0 = (int)fx0, iy0 = (int)fy0, iz0 = (int)fz0;
    float fx = ixf - fx0, fy = iyf - fy0, fz = izf - fz0;
    float occ = 0.0f;
    #pragma unroll
    for (int dzc = 0; dzc < 2; dzc++) {
        int cz = iz0 + dzc;
        if (cz < 0 || cz >= 128) continue;
        float wz = dzc ? fz : 1.0f - fz;
        #pragma unroll
        for (int dyc = 0; dyc < 2; dyc++) {
            int cy = iy0 + dyc;
            if (cy < 0 || cy >= 128) continue;
            float wy = dyc ? fy : 1.0f - fy;
            #pragma unroll
            for (int dxc = 0; dxc < 2; dxc++) {
                int cx = ix0 + dxc;
                if (cx < 0 || cx >= 128) continue;
                float wx = dxc ? fx : 1.0f - fx;
                occ += wz * wy * wx * __ldg(&grid[(cz << 14) + (cy << 7) + cx]);
            }
        }
    }
    return occ;
}

__global__ void __launch_bounds__(128, 5) nerf_render_kernel(
    const float* __restrict__ rays_o, const float* __restrict__ rays_d,
    const float* __restrict__ grid,
    const float* __restrict__ f_w1, const float* __restrict__ f_b1,
    const float* __restrict__ r_w1, const float* __restrict__ r_w2,
    const float* __restrict__ r_b2,
    float* __restrict__ out)
{
    extern __shared__ __align__(16) char smdyn[];
    __shared__ float wsumA[4], wsumB[4];
    __shared__ float wred[4][3];

    const int tid = threadIdx.x;
    const int wid = tid >> 5;
    const int lid = tid & 31;
    const int g   = lid >> 2;
    const int tq  = lid & 3;
    const int ray = blockIdx.x;

    const float ox = __ldg(&rays_o[ray * 3 + 0]);
    const float oy = __ldg(&rays_o[ray * 3 + 1]);
    const float oz = __ldg(&rays_o[ray * 3 + 2]);
    const float dx = __ldg(&rays_d[ray * 3 + 0]);
    const float dy = __ldg(&rays_d[ray * 3 + 1]);
    const float dz = __ldg(&rays_d[ray * 3 + 2]);

    // ---- EARLY: phase-B occupancy loads (hidden behind staging + phase A) ----
    bool mA, mB;
    {
        float pxA, pyA, pzA, pxB, pyB, pzB;
        ray_pos(tid, ox, oy, oz, dx, dy, dz, pxA, pyA, pzA);
        ray_pos(tid + 128, ox, oy, oz, dx, dy, dz, pxB, pyB, pzB);
        mA = sample_grid(grid, pxA, pyA, pzA) > OPACITY_TH;
        mB = sample_grid(grid, pxB, pyB, pzB) > OPACITY_TH;
    }

    // ---- staging ----
    {
        uint2* dstB = (uint2*)(smdyn + SM_BH);
        #pragma unroll
        for (int i = 0; i < 16; i++) dstB[tid + 128 * i] = g_Bh[tid + 128 * i];
        float* dw1b = (float*)(smdyn + SM_W1B);
        for (int i = tid; i < 512; i += 128) {
            int k = i >> 2, c = i & 3;
            dw1b[i] = (c < 3) ? f_w1[c * 128 + k] : f_b1[k];
        }
        ((float*)(smdyn + SM_WS))[tid] = g_ws[tid];
        if (tid < 64) {
            float hcv = g_hconst[tid]
                      + dx * r_w1[64 * 64 + tid]
                      + dy * r_w1[65 * 64 + tid]
                      + dz * r_w1[66 * 64 + tid];
            *(float4*)(smdyn + SM_RW2 + tid * 16) =
                make_float4(r_w2[tid * 3], r_w2[tid * 3 + 1], r_w2[tid * 3 + 2], hcv);
        }
        if (tid < 3)  ((float*)(smdyn + SM_MISC))[tid] = r_b2[tid];
        if (tid == 3) ((float*)(smdyn + SM_MISC))[3] = g_sconst[0];
    }
    __syncthreads();

    const float4* w1bv = (const float4*)(smdyn + SM_W1B);
    const float*  wsf  = (const float*)(smdyn + SM_WS);
    const uint2*  bp   = (const uint2*)(smdyn + SM_BH);
    const float4* qrw2 = (const float4*)(smdyn + SM_RW2);
    float*        sigb = (float*)(smdyn + SM_SIGB);
    float4*       rgbb = (float4*)(smdyn + SM_RGBB);
    const float rb0  = ((const float*)(smdyn + SM_MISC))[0];
    const float rb1  = ((const float*)(smdyn + SM_MISC))[1];
    const float rb2v = ((const float*)(smdyn + SM_MISC))[2];
    const float sconst = ((const float*)(smdyn + SM_MISC))[3];

    // ========== PHASE A: h build (fp16 hi/lo A) + sigma-dot + MMA + epilogue =
    #pragma unroll
    for (int mt = 0; mt < 4; mt++) {
        const int tt = wid * 4 + mt;
        const int r0 = 16 * tt + g;
        const int r1 = r0 + 8;

        float px0, py0, pz0, px1, py1, pz1;
        ray_pos(r0, ox, oy, oz, dx, dy, dz, px0, py0, pz0);
        ray_pos(r1, ox, oy, oz, dx, dy, dz, px1, py1, pz1);

        // A fragments: fp16 hi + fp16 residual (lo); sigma-dot partials (exact fp32)
        u32 ahi[8][4], alo[8][4];
        float sp0 = 0.0f, sp1 = 0.0f;
        #pragma unroll
        for (int kt = 0; kt < 8; kt++) {
            const int k0 = kt * 16 + 2 * tq;
            float4 wa = w1bv[k0],     wb = w1bv[k0 + 1];
            float4 wc = w1bv[k0 + 8], wd = w1bv[k0 + 9];
            float h00 = fmaxf(wa.w + px0 * wa.x + py0 * wa.y + pz0 * wa.z, 0.0f);
            float h01 = fmaxf(wb.w + px0 * wb.x + py0 * wb.y + pz0 * wb.z, 0.0f);
            float h08 = fmaxf(wc.w + px0 * wc.x + py0 * wc.y + pz0 * wc.z, 0.0f);
            float h09 = fmaxf(wd.w + px0 * wd.x + py0 * wd.y + pz0 * wd.z, 0.0f);
            float h10 = fmaxf(wa.w + px1 * wa.x + py1 * wa.y + pz1 * wa.z, 0.0f);
            float h11 = fmaxf(wb.w + px1 * wb.x + py1 * wb.y + pz1 * wb.z, 0.0f);
            float h18 = fmaxf(wc.w + px1 * wc.x + py1 * wc.y + pz1 * wc.z, 0.0f);
            float h19 = fmaxf(wd.w + px1 * wd.x + py1 * wd.y + pz1 * wd.z, 0.0f);
            float2 wsa = *(const float2*)&wsf[k0];
            float2 wsb = *(const float2*)&wsf[k0 + 8];
            sp0 = fmaf(h00, wsa.x, fmaf(h01, wsa.y, fmaf(h08, wsb.x, fmaf(h09, wsb.y, sp0))));
            sp1 = fmaf(h10, wsa.x, fmaf(h11, wsa.y, fmaf(h18, wsb.x, fmaf(h19, wsb.y, sp1))));
            u32 x0 = packh(h00, h01);
            u32 x1 = packh(h10, h11);
            u32 x2 = packh(h08, h09);
            u32 x3 = packh(h18, h19);
            ahi[kt][0] = x0; ahi[kt][1] = x1; ahi[kt][2] = x2; ahi[kt][3] = x3;
            float2 f0 = unpackh(x0), f1 = unpackh(x1), f2 = unpackh(x2), f3 = unpackh(x3);
            alo[kt][0] = packh(h00 - f0.x, h01 - f0.y);
            alo[kt][1] = packh(h10 - f1.x, h11 - f1.y);
            alo[kt][2] = packh(h08 - f2.x, h09 - f2.y);
            alo[kt][3] = packh(h18 - f3.x, h19 - f3.y);
        }
        // sigma-dot quad reduce
        sp0 += __shfl_xor_sync(0xffffffffu, sp0, 1);
        sp0 += __shfl_xor_sync(0xffffffffu, sp0, 2);
        sp1 += __shfl_xor_sync(0xffffffffu, sp1, 1);
        sp1 += __shfl_xor_sync(0xffffffffu, sp1, 2);
        if (tq == 0) { sigb[r0] = sp0; sigb[r1] = sp1; }

        float a00 = 0.0f, a01 = 0.0f, a02 = 0.0f;
        float a10 = 0.0f, a11 = 0.0f, a12 = 0.0f;
        #pragma unroll
        for (int nt = 0; nt < 8; nt++) {
            float p0 = 0.0f, p1 = 0.0f, p2 = 0.0f, p3 = 0.0f;   // ahi * b
            float q0 = 0.0f, q1 = 0.0f, q2 = 0.0f, q3 = 0.0f;   // alo * b
            const uint2* bnt = bp + nt * 256 + lid;
            #pragma unroll
            for (int kt = 0; kt < 8; kt++) {
                uint2 b = bnt[kt * 32];
                mma_f16(p0, p1, p2, p3, ahi[kt][0], ahi[kt][1], ahi[kt][2], ahi[kt][3], b.x, b.y);
                mma_f16(q0, q1, q2, q3, alo[kt][0], alo[kt][1], alo[kt][2], alo[kt][3], b.x, b.y);
            }
            float d0 = p0 + q0, d1 = p1 + q1;
            float d2 = p2 + q2, d3 = p3 + q3;
            const int c = nt * 8 + 2 * tq;
            float4 wA = qrw2[c], wB = qrw2[c + 1];
            float hA0 = fmaxf(d0 + wA.w, 0.0f);
            float hA1 = fmaxf(d1 + wB.w, 0.0f);
            float hB0 = fmaxf(d2 + wA.w, 0.0f);
            float hB1 = fmaxf(d3 + wB.w, 0.0f);
            a00 = fmaf(hA0, wA.x, fmaf(hA1, wB.x, a00));
            a01 = fmaf(hA0, wA.y, fmaf(hA1, wB.y, a01));
            a02 = fmaf(hA0, wA.z, fmaf(hA1, wB.z, a02));
            a10 = fmaf(hB0, wA.x, fmaf(hB1, wB.x, a10));
            a11 = fmaf(hB0, wA.y, fmaf(hB1, wB.y, a11));
            a12 = fmaf(hB0, wA.z, fmaf(hB1, wB.z, a12));
        }
        #pragma unroll
        for (int d = 1; d <= 2; d <<= 1) {
            a00 += __shfl_xor_sync(0xffffffffu, a00, d);
            a01 += __shfl_xor_sync(0xffffffffu, a01, d);
            a02 += __shfl_xor_sync(0xffffffffu, a02, d);
            a10 += __shfl_xor_sync(0xffffffffu, a10, d);
            a11 += __shfl_xor_sync(0xffffffffu, a11, d);
            a12 += __shfl_xor_sync(0xffffffffu, a12, d);
        }
        if (tq == 0) {
            rgbb[r0] = make_float4(1.0f / (1.0f + expf(-(a00 + rb0))),
                                   1.0f / (1.0f + expf(-(a01 + rb1))),
                                   1.0f / (1.0f + expf(-(a02 + rb2v))), 0.0f);
            rgbb[r1] = make_float4(1.0f / (1.0f + expf(-(a10 + rb0))),
                                   1.0f / (1.0f + expf(-(a11 + rb1))),
                                   1.0f / (1.0f + expf(-(a12 + rb2v))), 0.0f);
        }
    }
    __syncthreads();

    // ========== PHASE B: scan + weighted accumulation ========================
    float rgb0, rgb1, rgb2;
    {
        float tA  = tmap((float)tid * USTEP);
        float tA1 = tmap((float)(tid + 1) * USTEP);
        float tB  = tmap((float)(tid + 128) * USTEP);
        float tB1 = tmap((float)(tid + 129) * USTEP);
        float distA = tA1 - tA, distB = tB1 - tB;

        float preA = sigb[tid] + sconst;
        float preB = sigb[tid + 128] + sconst;
        float sigmaA = mA ? ((preA > 20.0f) ? preA : log1pf(expf(preA))) : 0.0f;
        float sigmaB = mB ? ((preB > 20.0f) ? preB : log1pf(expf(preB))) : 0.0f;

        float aA = -sigmaA * distA;
        float aB = -sigmaB * distB;
        float incA = aA, incB = aB;
        #pragma unroll
        for (int off = 1; off < 32; off <<= 1) {
            float yA = __shfl_up_sync(0xffffffffu, incA, off);
            float yB = __shfl_up_sync(0xffffffffu, incB, off);
            if (lid >= off) { incA += yA; incB += yB; }
        }
        if (lid == 31) { wsumA[wid] = incA; wsumB[wid] = incB; }
        __syncthreads();
        float offA = 0.0f, offB = 0.0f, totalA = 0.0f;
        #pragma unroll
        for (int i = 0; i < 4; i++) {
            float vA = wsumA[i];
            totalA += vA;
            if (i < wid) { offA += vA; offB += wsumB[i]; }
        }
        float exclA = offA + incA - aA;
        float exclB = totalA + offB + incB - aB;
        float transA = expf(exclA), transB = expf(exclB);
        float weightA = transA * (1.0f - expf(aA));
        float weightB = transB * (1.0f - expf(aB));
        float wA = (mA && transA > EARLY_TERM) ? weightA : 0.0f;
        float wB = (mB && transB > EARLY_TERM) ? weightB : 0.0f;

        float4 cA = rgbb[tid];
        float4 cB = rgbb[tid + 128];
        rgb0 = wA * cA.x + wB * cB.x;
        rgb1 = wA * cA.y + wB * cB.y;
        rgb2 = wA * cA.z + wB * cB.z;
    }

    // ---- deterministic block reduction ----
    #pragma unroll
    for (int off = 16; off > 0; off >>= 1) {
        rgb0 += __shfl_down_sync(0xffffffffu, rgb0, off);
        rgb1 += __shfl_down_sync(0xffffffffu, rgb1, off);
        rgb2 += __shfl_down_sync(0xffffffffu, rgb2, off);
    }
    if (lid == 0) { wred[wid][0] = rgb0; wred[wid][1] = rgb1; wred[wid][2] = rgb2; }
    __syncthreads();
    if (tid < 3) {
        float s = 0.0f;
        #pragma unroll
        for (int w = 0; w < 4; w++) s += wred[w][tid];
        out[ray * 3 + tid] = s;
    }
}

extern "C" void kernel_launch(void* const* d_in, const int* in_sizes, int n_in,
                              void* d_out, int out_size) {
    const float* rays_o = (const float*)d_in[0];
    const float* rays_d = (const float*)d_in[1];
    const float* grid   = (const float*)d_in[2];
    const float* f_w1   = (const float*)d_in[3];
    const float* f_b1   = (const float*)d_in[4];
    const float* f_w2   = (const float*)d_in[5];
    const float* f_b2   = (const float*)d_in[6];
    const float* s_w    = (const float*)d_in[7];
    const float* s_b    = (const float*)d_in[8];
    const float* r_w1   = (const float*)d_in[9];
    const float* r_b1   = (const float*)d_in[10];
    const float* r_w2   = (const float*)d_in[11];
    const float* r_b2   = (const float*)d_in[12];
    float* out = (float*)d_out;

    const int n_rays = in_sizes[0] / 3;

    prep_kernel<<<(2241 + 255) / 256, 256>>>(f_w2, f_b2, s_w, s_b, r_w1, r_b1);

    cudaFuncSetAttribute(nerf_render_kernel,
                         cudaFuncAttributeMaxDynamicSharedMemorySize, SMEM_BYTES);
    nerf_render_kernel<<<n_rays, 128, SMEM_BYTES>>>(
        rays_o, rays_d, grid, f_w1, f_b1, r_w1, r_w2, r_b2, out);
}

// round 11
// speedup vs baseline: 1.6456x; 1.3439x over previous
#include <cuda_runtime.h>
#include <cuda_fp16.h>
#include <math.h>

typedef unsigned int u32;

#define OPACITY_TH 0.01f
#define EARLY_TERM 1e-4f

// pack two floats to f16x2: low16 = f16(lo_f), high16 = f16(hi_f)
__device__ __forceinline__ u32 packh(float lo_f, float hi_f) {
    __half2 h = __halves2half2(__float2half_rn(lo_f), __float2half_rn(hi_f));
    return *reinterpret_cast<u32*>(&h);
}

__device__ __forceinline__ void mma_f16(float& d0, float& d1, float& d2, float& d3,
                                        u32 a0, u32 a1, u32 a2, u32 a3,
                                        u32 b0, u32 b1) {
    asm volatile("mma.sync.aligned.m16n8k16.row.col.f32.f16.f16.f32 "
        "{%0,%1,%2,%3}, {%4,%5,%6,%7}, {%8,%9}, {%0,%1,%2,%3};"
        : "+f"(d0), "+f"(d1), "+f"(d2), "+f"(d3)
        : "r"(a0), "r"(a1), "r"(a2), "r"(a3), "r"(b0), "r"(b1));
}

// ---------------- precomputed globals (prep kernel output) ----------------
// B fragments (fp16): fid = nt*8+kt, lane l: n = nt*8+(l>>2), tq=l&3, k0=kt*16+2tq
//   uint2 = { bh(k0,k0+1), bh(k0+8,k0+9) }
__device__ __align__(16) uint2 g_Bh[64 * 32];
__device__ float g_ws[128];      // f_w2[k,:]·s_w
__device__ float g_hconst[64];   // f_b2 @ r_w1[:64,:] + r_b1
__device__ float g_sconst[1];    // f_b2·s_w + s_b

__global__ void prep_kernel(const float* __restrict__ f_w2, const float* __restrict__ f_b2,
                            const float* __restrict__ s_w,  const float* __restrict__ s_b,
                            const float* __restrict__ r_w1, const float* __restrict__ r_b1)
{
    int i = blockIdx.x * blockDim.x + threadIdx.x;
    if (i < 2048) {
        int fid = i >> 5, lane = i & 31;
        int nt = fid >> 3, kt = fid & 7;
        int n = nt * 8 + (lane >> 2);
        int tq = lane & 3;
        int k0 = kt * 16 + 2 * tq;
        float v[4];
        #pragma unroll
        for (int e = 0; e < 4; e++) {
            int k = k0 + (e >> 1) * 8 + (e & 1);   // k0, k0+1, k0+8, k0+9
            float s = 0.0f;
            #pragma unroll 8
            for (int t = 0; t < 64; t++) s += f_w2[k * 64 + t] * r_w1[t * 64 + n];
            v[e] = s;
        }
        uint2 o;
        o.x = packh(v[0], v[1]);
        o.y = packh(v[2], v[3]);
        g_Bh[fid * 32 + lane] = o;
    } else if (i < 2176) {
        int k = i - 2048;
        float s = 0.0f;
        #pragma unroll 8
        for (int t = 0; t < 64; t++) s += f_w2[k * 64 + t] * s_w[t];
        g_ws[k] = s;
    } else if (i < 2240) {
        int j = i - 2176;
        float s = r_b1[j];
        #pragma unroll 8
        for (int t = 0; t < 64; t++) s += f_b2[t] * r_w1[t * 64 + j];
        g_hconst[j] = s;
    } else if (i == 2240) {
        float s = s_b[0];
        for (int t = 0; t < 64; t++) s += f_b2[t] * s_w[t];
        g_sconst[0] = s;
    }
}

// ---------------- dynamic shared layout (bytes) ----------------
#define SM_BH    0        // 16KB uint2[2048]
#define SM_W1B   16384    // [128][4] f32 2KB
#define SM_WS    18432    // 512B
#define SM_RW2   18944    // [64][4] 1KB
#define SM_SIGB  19968    // sigma_pre[256] 1KB
#define SM_RGBB  20992    // rgbRaw[256] float4 4KB
#define SM_MISC  25088    // [0..2]=r_b2, [3]=sconst
#define SMEM_BYTES 25104

__device__ __forceinline__ float tmap(float u) {
    return (u < 0.5f) ? 2.0f * u : 1.0f / (2.0f - 2.0f * u);
}

#define USTEP ((257.0f / 258.0f) / 256.0f)

__device__ __forceinline__ void ray_pos(int s, float ox, float oy, float oz,
                                        float dx, float dy, float dz,
                                        float& px, float& py, float& pz) {
    float tv = tmap((float)s * USTEP);
    px = ox + dx * tv; py = oy + dy * tv; pz = oz + dz * tv;
    float nrm = sqrtf(px * px + py * py + pz * pz);
    float cs = (nrm <= 1.0f) ? 0.5f : (2.0f - 1.0f / nrm) / nrm * 0.5f;
    px *= cs; py *= cs; pz *= cs;
}

__device__ __forceinline__ float sample_grid(const float* __restrict__ grid,
                                             float px, float py, float pz) {
    float ixf = ((px + 1.0f) * 128.0f - 1.0f) * 0.5f;
    float iyf = ((py + 1.0f) * 128.0f - 1.0f) * 0.5f;
    float izf = ((pz + 1.0f) * 128.0f - 1.0f) * 0.5f;
    float fx0 = floorf(ixf), fy0 = floorf(iyf), fz0 = floorf(izf);
    int ix0 = (int)fx0, iy0 = (int)fy0, iz0 = (int)fz0;
    float fx = ixf - fx0, fy = iyf - fy0, fz = izf - fz0;
    float occ = 0.0f;
    #pragma unroll
    for (int dzc = 0; dzc < 2; dzc++) {
        int cz = iz0 + dzc;
        if (cz < 0 || cz >= 128) continue;
        float wz = dzc ? fz : 1.0f - fz;
        #pragma unroll
        for (int dyc = 0; dyc < 2; dyc++) {
            int cy = iy0 + dyc;
            if (cy < 0 || cy >= 128) continue;
            float wy = dyc ? fy : 1.0f - fy;
            #pragma unroll
            for (int dxc = 0; dxc < 2; dxc++) {
                int cx = ix0 + dxc;
                if (cx < 0 || cx >= 128) continue;
                float wx = dxc ? fx : 1.0f - fx;
                occ += wz * wy * wx * __ldg(&grid[(cz << 14) + (cy << 7) + cx]);
            }
        }
    }
    return occ;
}

__global__ void __launch_bounds__(128, 5) nerf_render_kernel(
    const float* __restrict__ rays_o, const float* __restrict__ rays_d,
    const float* __restrict__ grid,
    const float* __restrict__ f_w1, const float* __restrict__ f_b1,
    const float* __restrict__ r_w1, const float* __restrict__ r_w2,
    const float* __restrict__ r_b2,
    float* __restrict__ out)
{
    extern __shared__ __align__(16) char smdyn[];
    __shared__ float wsumA[4], wsumB[4];
    __shared__ float wred[4][3];

    const int tid = threadIdx.x;
    const int wid = tid >> 5;
    const int lid = tid & 31;
    const int g   = lid >> 2;
    const int tq  = lid & 3;
    const int ray = blockIdx.x;

    const float ox = __ldg(&rays_o[ray * 3 + 0]);
    const float oy = __ldg(&rays_o[ray * 3 + 1]);
    const float oz = __ldg(&rays_o[ray * 3 + 2]);
    const float dx = __ldg(&rays_d[ray * 3 + 0]);
    const float dy = __ldg(&rays_d[ray * 3 + 1]);
    const float dz = __ldg(&rays_d[ray * 3 + 2]);

    // ---- EARLY: phase-B occupancy loads (hidden behind staging + phase A) ----
    bool mA, mB;
    {
        float pxA, pyA, pzA, pxB, pyB, pzB;
        ray_pos(tid, ox, oy, oz, dx, dy, dz, pxA, pyA, pzA);
        ray_pos(tid + 128, ox, oy, oz, dx, dy, dz, pxB, pyB, pzB);
        mA = sample_grid(grid, pxA, pyA, pzA) > OPACITY_TH;
        mB = sample_grid(grid, pxB, pyB, pzB) > OPACITY_TH;
    }

    // ---- staging ----
    {
        uint2* dstB = (uint2*)(smdyn + SM_BH);
        #pragma unroll
        for (int i = 0; i < 16; i++) dstB[tid + 128 * i] = g_Bh[tid + 128 * i];
        float* dw1b = (float*)(smdyn + SM_W1B);
        for (int i = tid; i < 512; i += 128) {
            int k = i >> 2, c = i & 3;
            dw1b[i] = (c < 3) ? f_w1[c * 128 + k] : f_b1[k];
        }
        ((float*)(smdyn + SM_WS))[tid] = g_ws[tid];
        if (tid < 64) {
            float hcv = g_hconst[tid]
                      + dx * r_w1[64 * 64 + tid]
                      + dy * r_w1[65 * 64 + tid]
                      + dz * r_w1[66 * 64 + tid];
            *(float4*)(smdyn + SM_RW2 + tid * 16) =
                make_float4(r_w2[tid * 3], r_w2[tid * 3 + 1], r_w2[tid * 3 + 2], hcv);
        }
        if (tid < 3)  ((float*)(smdyn + SM_MISC))[tid] = r_b2[tid];
        if (tid == 3) ((float*)(smdyn + SM_MISC))[3] = g_sconst[0];
    }
    __syncthreads();

    const float4* w1bv = (const float4*)(smdyn + SM_W1B);
    const float*  wsf  = (const float*)(smdyn + SM_WS);
    const uint2*  bp   = (const uint2*)(smdyn + SM_BH);
    const float4* qrw2 = (const float4*)(smdyn + SM_RW2);
    float*        sigb = (float*)(smdyn + SM_SIGB);
    float4*       rgbb = (float4*)(smdyn + SM_RGBB);
    const float rb0  = ((const float*)(smdyn + SM_MISC))[0];
    const float rb1  = ((const float*)(smdyn + SM_MISC))[1];
    const float rb2v = ((const float*)(smdyn + SM_MISC))[2];
    const float sconst = ((const float*)(smdyn + SM_MISC))[3];

    // ========== PHASE A: h build (fp16 A, single pass) + sigma-dot + MMA =====
    #pragma unroll
    for (int mt = 0; mt < 4; mt++) {
        const int tt = wid * 4 + mt;
        const int r0 = 16 * tt + g;
        const int r1 = r0 + 8;

        float px0, py0, pz0, px1, py1, pz1;
        ray_pos(r0, ox, oy, oz, dx, dy, dz, px0, py0, pz0);
        ray_pos(r1, ox, oy, oz, dx, dy, dz, px1, py1, pz1);

        // A fragments: single fp16; sigma-dot partials stay exact fp32
        u32 af[8][4];
        float sp0 = 0.0f, sp1 = 0.0f;
        #pragma unroll
        for (int kt = 0; kt < 8; kt++) {
            const int k0 = kt * 16 + 2 * tq;
            float4 wa = w1bv[k0],     wb = w1bv[k0 + 1];
            float4 wc = w1bv[k0 + 8], wd = w1bv[k0 + 9];
            float h00 = fmaxf(wa.w + px0 * wa.x + py0 * wa.y + pz0 * wa.z, 0.0f);
            float h01 = fmaxf(wb.w + px0 * wb.x + py0 * wb.y + pz0 * wb.z, 0.0f);
            float h08 = fmaxf(wc.w + px0 * wc.x + py0 * wc.y + pz0 * wc.z, 0.0f);
            float h09 = fmaxf(wd.w + px0 * wd.x + py0 * wd.y + pz0 * wd.z, 0.0f);
            float h10 = fmaxf(wa.w + px1 * wa.x + py1 * wa.y + pz1 * wa.z, 0.0f);
            float h11 = fmaxf(wb.w + px1 * wb.x + py1 * wb.y + pz1 * wb.z, 0.0f);
            float h18 = fmaxf(wc.w + px1 * wc.x + py1 * wc.y + pz1 * wc.z, 0.0f);
            float h19 = fmaxf(wd.w + px1 * wd.x + py1 * wd.y + pz1 * wd.z, 0.0f);
            float2 wsa = *(const float2*)&wsf[k0];
            float2 wsb = *(const float2*)&wsf[k0 + 8];
            sp0 = fmaf(h00, wsa.x, fmaf(h01, wsa.y, fmaf(h08, wsb.x, fmaf(h09, wsb.y, sp0))));
            sp1 = fmaf(h10, wsa.x, fmaf(h11, wsa.y, fmaf(h18, wsb.x, fmaf(h19, wsb.y, sp1))));
            af[kt][0] = packh(h00, h01);
            af[kt][1] = packh(h10, h11);
            af[kt][2] = packh(h08, h09);
            af[kt][3] = packh(h18, h19);
        }
        // sigma-dot quad reduce
        sp0 += __shfl_xor_sync(0xffffffffu, sp0, 1);
        sp0 += __shfl_xor_sync(0xffffffffu, sp0, 2);
        sp1 += __shfl_xor_sync(0xffffffffu, sp1, 1);
        sp1 += __shfl_xor_sync(0xffffffffu, sp1, 2);
        if (tq == 0) { sigb[r0] = sp0; sigb[r1] = sp1; }

        float a00 = 0.0f, a01 = 0.0f, a02 = 0.0f;
        float a10 = 0.0f, a11 = 0.0f, a12 = 0.0f;
        #pragma unroll
        for (int nt = 0; nt < 8; nt++) {
            float d0 = 0.0f, d1 = 0.0f, d2 = 0.0f, d3 = 0.0f;
            const uint2* bnt = bp + nt * 256 + lid;
            #pragma unroll
            for (int kt = 0; kt < 8; kt++) {
                uint2 b = bnt[kt * 32];
                mma_f16(d0, d1, d2, d3, af[kt][0], af[kt][1], af[kt][2], af[kt][3], b.x, b.y);
            }
            const int c = nt * 8 + 2 * tq;
            float4 wA = qrw2[c], wB = qrw2[c + 1];
            float hA0 = fmaxf(d0 + wA.w, 0.0f);
            float hA1 = fmaxf(d1 + wB.w, 0.0f);
            float hB0 = fmaxf(d2 + wA.w, 0.0f);
            float hB1 = fmaxf(d3 + wB.w, 0.0f);
            a00 = fmaf(hA0, wA.x, fmaf(hA1, wB.x, a00));
            a01 = fmaf(hA0, wA.y, fmaf(hA1, wB.y, a01));
            a02 = fmaf(hA0, wA.z, fmaf(hA1, wB.z, a02));
            a10 = fmaf(hB0, wA.x, fmaf(hB1, wB.x, a10));
            a11 = fmaf(hB0, wA.y, fmaf(hB1, wB.y, a11));
            a12 = fmaf(hB0, wA.z, fmaf(hB1, wB.z, a12));
        }
        #pragma unroll
        for (int d = 1; d <= 2; d <<= 1) {
            a00 += __shfl_xor_sync(0xffffffffu, a00, d);
            a01 += __shfl_xor_sync(0xffffffffu, a01, d);
            a02 += __shfl_xor_sync(0xffffffffu, a02, d);
            a10 += __shfl_xor_sync(0xffffffffu, a10, d);
            a11 += __shfl_xor_sync(0xffffffffu, a11, d);
            a12 += __shfl_xor_sync(0xffffffffu, a12, d);
        }
        if (tq == 0) {
            rgbb[r0] = make_float4(1.0f / (1.0f + expf(-(a00 + rb0))),
                                   1.0f / (1.0f + expf(-(a01 + rb1))),
                                   1.0f / (1.0f + expf(-(a02 + rb2v))), 0.0f);
            rgbb[r1] = make_float4(1.0f / (1.0f + expf(-(a10 + rb0))),
                                   1.0f / (1.0f + expf(-(a11 + rb1))),
                                   1.0f / (1.0f + expf(-(a12 + rb2v))), 0.0f);
        }
    }
    __syncthreads();

    // ========== PHASE B: scan + weighted accumulation ========================
    float rgb0, rgb1, rgb2;
    {
        float tA  = tmap((float)tid * USTEP);
        float tA1 = tmap((float)(tid + 1) * USTEP);
        float tB  = tmap((float)(tid + 128) * USTEP);
        float tB1 = tmap((float)(tid + 129) * USTEP);
        float distA = tA1 - tA, distB = tB1 - tB;

        float preA = sigb[tid] + sconst;
        float preB = sigb[tid + 128] + sconst;
        float sigmaA = mA ? ((preA > 20.0f) ? preA : log1pf(expf(preA))) : 0.0f;
        float sigmaB = mB ? ((preB > 20.0f) ? preB : log1pf(expf(preB))) : 0.0f;

        float aA = -sigmaA * distA;
        float aB = -sigmaB * distB;
        float incA = aA, incB = aB;
        #pragma unroll
        for (int off = 1; off < 32; off <<= 1) {
            float yA = __shfl_up_sync(0xffffffffu, incA, off);
            float yB = __shfl_up_sync(0xffffffffu, incB, off);
            if (lid >= off) { incA += yA; incB += yB; }
        }
        if (lid == 31) { wsumA[wid] = incA; wsumB[wid] = incB; }
        __syncthreads();
        float offA = 0.0f, offB = 0.0f, totalA = 0.0f;
        #pragma unroll
        for (int i = 0; i < 4; i++) {
            float vA = wsumA[i];
            totalA += vA;
            if (i < wid) { offA += vA; offB += wsumB[i]; }
        }
        float exclA = offA + incA - aA;
        float exclB = totalA + offB + incB - aB;
        float transA = expf(exclA), transB = expf(exclB);
        float weightA = transA * (1.0f - expf(aA));
        float weightB = transB * (1.0f - expf(aB));
        float wA = (mA && transA > EARLY_TERM) ? weightA : 0.0f;
        float wB = (mB && transB > EARLY_TERM) ? weightB : 0.0f;

        float4 cA = rgbb[tid];
        float4 cB = rgbb[tid + 128];
        rgb0 = wA * cA.x + wB * cB.x;
        rgb1 = wA * cA.y + wB * cB.y;
        rgb2 = wA * cA.z + wB * cB.z;
    }

    // ---- deterministic block reduction ----
    #pragma unroll
    for (int off = 16; off > 0; off >>= 1) {
        rgb0 += __shfl_down_sync(0xffffffffu, rgb0, off);
        rgb1 += __shfl_down_sync(0xffffffffu, rgb1, off);
        rgb2 += __shfl_down_sync(0xffffffffu, rgb2, off);
    }
    if (lid == 0) { wred[wid][0] = rgb0; wred[wid][1] = rgb1; wred[wid][2] = rgb2; }
    __syncthreads();
    if (tid < 3) {
        float s = 0.0f;
        #pragma unroll
        for (int w = 0; w < 4; w++) s += wred[w][tid];
        out[ray * 3 + tid] = s;
    }
}

extern "C" void kernel_launch(void* const* d_in, const int* in_sizes, int n_in,
                              void* d_out, int out_size) {
    const float* rays_o = (const float*)d_in[0];
    const float* rays_d = (const float*)d_in[1];
    const float* grid   = (const float*)d_in[2];
    const float* f_w1   = (const float*)d_in[3];
    const float* f_b1   = (const float*)d_in[4];
    const float* f_w2   = (const float*)d_in[5];
    const float* f_b2   = (const float*)d_in[6];
    const float* s_w    = (const float*)d_in[7];
    const float* s_b    = (const float*)d_in[8];
    const float* r_w1   = (const float*)d_in[9];
    const float* r_b1   = (const float*)d_in[10];
    const float* r_w2   = (const float*)d_in[11];
    const float* r_b2   = (const float*)d_in[12];
    float* out = (float*)d_out;

    const int n_rays = in_sizes[0] / 3;

    prep_kernel<<<(2241 + 255) / 256, 256>>>(f_w2, f_b2, s_w, s_b, r_w1, r_b1);

    cudaFuncSetAttribute(nerf_render_kernel,
                         cudaFuncAttributeMaxDynamicSharedMemorySize, SMEM_BYTES);
    nerf_render_kernel<<<n_rays, 128, SMEM_BYTES>>>(
        rays_o, rays_d, grid, f_w1, f_b1, r_w1, r_w2, r_b2, out);
}

// round 12
// speedup vs baseline: 1.6865x; 1.0249x over previous
#include <cuda_runtime.h>
#include <cuda_fp16.h>
#include <math.h>

typedef unsigned int u32;

#define OPACITY_TH 0.01f
#define EARLY_TERM 1e-4f

// pack two floats to f16x2: low16 = f16(lo_f), high16 = f16(hi_f)
__device__ __forceinline__ u32 packh(float lo_f, float hi_f) {
    __half2 h = __halves2half2(__float2half_rn(lo_f), __float2half_rn(hi_f));
    return *reinterpret_cast<u32*>(&h);
}

__device__ __forceinline__ void mma_f16(float& d0, float& d1, float& d2, float& d3,
                                        u32 a0, u32 a1, u32 a2, u32 a3,
                                        u32 b0, u32 b1) {
    asm volatile("mma.sync.aligned.m16n8k16.row.col.f32.f16.f16.f32 "
        "{%0,%1,%2,%3}, {%4,%5,%6,%7}, {%8,%9}, {%0,%1,%2,%3};"
        : "+f"(d0), "+f"(d1), "+f"(d2), "+f"(d3)
        : "r"(a0), "r"(a1), "r"(a2), "r"(a3), "r"(b0), "r"(b1));
}

// ---------------- precomputed globals (prep kernel output) ----------------
// B fragments (fp16), nt-PAIRED: for ntp = nt>>1, kt, lane:
//   u32[ ((ntp*8+kt)*32+lane)*4 + (nt&1)*2 + {0,1} ] = { bh(k0,k0+1), bh(k0+8,k0+9) }
//   so uint4 at (ntp,kt,lane) = { ntEven.x, ntEven.y, ntOdd.x, ntOdd.y }
__device__ __align__(16) u32 g_Bq[4096];
__device__ float g_ws[128];      // f_w2[k,:]·s_w
__device__ float g_hconst[64];   // f_b2 @ r_w1[:64,:] + r_b1
__device__ float g_sconst[1];    // f_b2·s_w + s_b

__global__ void prep_kernel(const float* __restrict__ f_w2, const float* __restrict__ f_b2,
                            const float* __restrict__ s_w,  const float* __restrict__ s_b,
                            const float* __restrict__ r_w1, const float* __restrict__ r_b1)
{
    int i = blockIdx.x * blockDim.x + threadIdx.x;
    if (i < 2048) {
        int fid = i >> 5, lane = i & 31;
        int nt = fid >> 3, kt = fid & 7;
        int n = nt * 8 + (lane >> 2);
        int tq = lane & 3;
        int k0 = kt * 16 + 2 * tq;
        float v[4];
        #pragma unroll
        for (int e = 0; e < 4; e++) {
            int k = k0 + (e >> 1) * 8 + (e & 1);   // k0, k0+1, k0+8, k0+9
            float s = 0.0f;
            #pragma unroll 8
            for (int t = 0; t < 64; t++) s += f_w2[k * 64 + t] * r_w1[t * 64 + n];
            v[e] = s;
        }
        int ntp = nt >> 1;
        int base = ((ntp * 8 + kt) * 32 + lane) * 4 + (nt & 1) * 2;
        g_Bq[base + 0] = packh(v[0], v[1]);
        g_Bq[base + 1] = packh(v[2], v[3]);
    } else if (i < 2176) {
        int k = i - 2048;
        float s = 0.0f;
        #pragma unroll 8
        for (int t = 0; t < 64; t++) s += f_w2[k * 64 + t] * s_w[t];
        g_ws[k] = s;
    } else if (i < 2240) {
        int j = i - 2176;
        float s = r_b1[j];
        #pragma unroll 8
        for (int t = 0; t < 64; t++) s += f_b2[t] * r_w1[t * 64 + j];
        g_hconst[j] = s;
    } else if (i == 2240) {
        float s = s_b[0];
        for (int t = 0; t < 64; t++) s += f_b2[t] * s_w[t];
        g_sconst[0] = s;
    }
}

// ---------------- dynamic shared layout (bytes) ----------------
#define SM_BQ    0        // 16KB u32[4096] (uint4-paired)
#define SM_W1B   16384    // [128][4] f32 2KB
#define SM_WS    18432    // 512B
#define SM_RW2   18944    // [64][4] 1KB
#define SM_SIGB  19968    // sigma_pre[256] 1KB
#define SM_RGBB  20992    // rgbRaw[256] float4 4KB
#define SM_MISC  25088    // [0..2]=r_b2, [3]=sconst
#define SMEM_BYTES 25104

__device__ __forceinline__ float tmap(float u) {
    return (u < 0.5f) ? 2.0f * u : 1.0f / (2.0f - 2.0f * u);
}

#define USTEP ((257.0f / 258.0f) / 256.0f)

__device__ __forceinline__ void ray_pos(int s, float ox, float oy, float oz,
                                        float dx, float dy, float dz,
                                        float& px, float& py, float& pz) {
    float tv = tmap((float)s * USTEP);
    px = ox + dx * tv; py = oy + dy * tv; pz = oz + dz * tv;
    float nrm = sqrtf(px * px + py * py + pz * pz);
    float cs = (nrm <= 1.0f) ? 0.5f : (2.0f - 1.0f / nrm) / nrm * 0.5f;
    px *= cs; py *= cs; pz *= cs;
}

__device__ __forceinline__ float sample_grid(const float* __restrict__ grid,
                                             float px, float py, float pz) {
    float ixf = ((px + 1.0f) * 128.0f - 1.0f) * 0.5f;
    float iyf = ((py + 1.0f) * 128.0f - 1.0f) * 0.5f;
    float izf = ((pz + 1.0f) * 128.0f - 1.0f) * 0.5f;
    float fx0 = floorf(ixf), fy0 = floorf(iyf), fz0 = floorf(izf);
    int ix0 = (int)fx0, iy0 = (int)fy0, iz0 = (int)fz0;
    float fx = ixf - fx0, fy = iyf - fy0, fz = izf - fz0;
    float occ = 0.0f;
    #pragma unroll
    for (int dzc = 0; dzc < 2; dzc++) {
        int cz = iz0 + dzc;
        if (cz < 0 || cz >= 128) continue;
        float wz = dzc ? fz : 1.0f - fz;
        #pragma unroll
        for (int dyc = 0; dyc < 2; dyc++) {
            int cy = iy0 + dyc;
            if (cy < 0 || cy >= 128) continue;
            float wy = dyc ? fy : 1.0f - fy;
            #pragma unroll
            for (int dxc = 0; dxc < 2; dxc++) {
                int cx = ix0 + dxc;
                if (cx < 0 || cx >= 128) continue;
                float wx = dxc ? fx : 1.0f - fx;
                occ += wz * wy * wx * __ldg(&grid[(cz << 14) + (cy << 7) + cx]);
            }
        }
    }
    return occ;
}

__global__ void __launch_bounds__(128, 4) nerf_render_kernel(
    const float* __restrict__ rays_o, const float* __restrict__ rays_d,
    const float* __restrict__ grid,
    const float* __restrict__ f_w1, const float* __restrict__ f_b1,
    const float* __restrict__ r_w1, const float* __restrict__ r_w2,
    const float* __restrict__ r_b2,
    float* __restrict__ out)
{
    extern __shared__ __align__(16) char smdyn[];
    __shared__ float wsumA[4], wsumB[4];
    __shared__ float wred[4][3];

    const int tid = threadIdx.x;
    const int wid = tid >> 5;
    const int lid = tid & 31;
    const int g   = lid >> 2;
    const int tq  = lid & 3;
    const int ray = blockIdx.x;

    const float ox = __ldg(&rays_o[ray * 3 + 0]);
    const float oy = __ldg(&rays_o[ray * 3 + 1]);
    const float oz = __ldg(&rays_o[ray * 3 + 2]);
    const float dx = __ldg(&rays_d[ray * 3 + 0]);
    const float dy = __ldg(&rays_d[ray * 3 + 1]);
    const float dz = __ldg(&rays_d[ray * 3 + 2]);

    // ---- EARLY: phase-B occupancy loads (hidden behind staging + phase A) ----
    bool mA, mB;
    {
        float pxA, pyA, pzA, pxB, pyB, pzB;
        ray_pos(tid, ox, oy, oz, dx, dy, dz, pxA, pyA, pzA);
        ray_pos(tid + 128, ox, oy, oz, dx, dy, dz, pxB, pyB, pzB);
        mA = sample_grid(grid, pxA, pyA, pzA) > OPACITY_TH;
        mB = sample_grid(grid, pxB, pyB, pzB) > OPACITY_TH;
    }

    // ---- staging ----
    {
        uint4* dstB = (uint4*)(smdyn + SM_BQ);
        const uint4* srcB = (const uint4*)g_Bq;
        #pragma unroll
        for (int i = 0; i < 8; i++) dstB[tid + 128 * i] = srcB[tid + 128 * i];
        float* dw1b = (float*)(smdyn + SM_W1B);
        for (int i = tid; i < 512; i += 128) {
            int k = i >> 2, c = i & 3;
            dw1b[i] = (c < 3) ? f_w1[c * 128 + k] : f_b1[k];
        }
        ((float*)(smdyn + SM_WS))[tid] = g_ws[tid];
        if (tid < 64) {
            float hcv = g_hconst[tid]
                      + dx * r_w1[64 * 64 + tid]
                      + dy * r_w1[65 * 64 + tid]
                      + dz * r_w1[66 * 64 + tid];
            *(float4*)(smdyn + SM_RW2 + tid * 16) =
                make_float4(r_w2[tid * 3], r_w2[tid * 3 + 1], r_w2[tid * 3 + 2], hcv);
        }
        if (tid < 3)  ((float*)(smdyn + SM_MISC))[tid] = r_b2[tid];
        if (tid == 3) ((float*)(smdyn + SM_MISC))[3] = g_sconst[0];
    }
    __syncthreads();

    const float4* w1bv = (const float4*)(smdyn + SM_W1B);
    const float*  wsf  = (const float*)(smdyn + SM_WS);
    const uint4*  bp   = (const uint4*)(smdyn + SM_BQ);
    const float4* qrw2 = (const float4*)(smdyn + SM_RW2);
    float*        sigb = (float*)(smdyn + SM_SIGB);
    float4*       rgbb = (float4*)(smdyn + SM_RGBB);
    const float rb0  = ((const float*)(smdyn + SM_MISC))[0];
    const float rb1  = ((const float*)(smdyn + SM_MISC))[1];
    const float rb2v = ((const float*)(smdyn + SM_MISC))[2];
    const float sconst = ((const float*)(smdyn + SM_MISC))[3];

    // ========== PHASE A: 2 M-tiles per pass; B/w1 loads amortized ============
    // warp wid owns tiles wid*4 .. wid*4+3; processes them in pairs.
    #pragma unroll
    for (int mtp = 0; mtp < 2; mtp++) {
        const int tt0 = wid * 4 + 2 * mtp;       // tile pair
        const int r0 = 16 * tt0 + g;             // tile0 rows r0, r0+8
        const int r1 = r0 + 8;
        const int r2 = r0 + 16;                  // tile1 rows
        const int r3 = r0 + 24;

        float px0, py0, pz0, px1, py1, pz1, px2, py2, pz2, px3, py3, pz3;
        ray_pos(r0, ox, oy, oz, dx, dy, dz, px0, py0, pz0);
        ray_pos(r1, ox, oy, oz, dx, dy, dz, px1, py1, pz1);
        ray_pos(r2, ox, oy, oz, dx, dy, dz, px2, py2, pz2);
        ray_pos(r3, ox, oy, oz, dx, dy, dz, px3, py3, pz3);

        // A fragments for both tiles (fp16); sigma-dot partials exact fp32
        u32 af0[8][4], af1[8][4];
        float sp0 = 0.0f, sp1 = 0.0f, sp2 = 0.0f, sp3 = 0.0f;
        #pragma unroll
        for (int kt = 0; kt < 8; kt++) {
            const int k0 = kt * 16 + 2 * tq;
            float4 wa = w1bv[k0],     wb = w1bv[k0 + 1];
            float4 wc = w1bv[k0 + 8], wd = w1bv[k0 + 9];
            float h00 = fmaxf(wa.w + px0 * wa.x + py0 * wa.y + pz0 * wa.z, 0.0f);
            float h01 = fmaxf(wb.w + px0 * wb.x + py0 * wb.y + pz0 * wb.z, 0.0f);
            float h08 = fmaxf(wc.w + px0 * wc.x + py0 * wc.y + pz0 * wc.z, 0.0f);
            float h09 = fmaxf(wd.w + px0 * wd.x + py0 * wd.y + pz0 * wd.z, 0.0f);
            float h10 = fmaxf(wa.w + px1 * wa.x + py1 * wa.y + pz1 * wa.z, 0.0f);
            float h11 = fmaxf(wb.w + px1 * wb.x + py1 * wb.y + pz1 * wb.z, 0.0f);
            float h18 = fmaxf(wc.w + px1 * wc.x + py1 * wc.y + pz1 * wc.z, 0.0f);
            float h19 = fmaxf(wd.w + px1 * wd.x + py1 * wd.y + pz1 * wd.z, 0.0f);
            float h20 = fmaxf(wa.w + px2 * wa.x + py2 * wa.y + pz2 * wa.z, 0.0f);
            float h21 = fmaxf(wb.w + px2 * wb.x + py2 * wb.y + pz2 * wb.z, 0.0f);
            float h28 = fmaxf(wc.w + px2 * wc.x + py2 * wc.y + pz2 * wc.z, 0.0f);
            float h29 = fmaxf(wd.w + px2 * wd.x + py2 * wd.y + pz2 * wd.z, 0.0f);
            float h30 = fmaxf(wa.w + px3 * wa.x + py3 * wa.y + pz3 * wa.z, 0.0f);
            float h31 = fmaxf(wb.w + px3 * wb.x + py3 * wb.y + pz3 * wb.z, 0.0f);
            float h38 = fmaxf(wc.w + px3 * wc.x + py3 * wc.y + pz3 * wc.z, 0.0f);
            float h39 = fmaxf(wd.w + px3 * wd.x + py3 * wd.y + pz3 * wd.z, 0.0f);
            float2 wsa = *(const float2*)&wsf[k0];
            float2 wsb = *(const float2*)&wsf[k0 + 8];
            sp0 = fmaf(h00, wsa.x, fmaf(h01, wsa.y, fmaf(h08, wsb.x, fmaf(h09, wsb.y, sp0))));
            sp1 = fmaf(h10, wsa.x, fmaf(h11, wsa.y, fmaf(h18, wsb.x, fmaf(h19, wsb.y, sp1))));
            sp2 = fmaf(h20, wsa.x, fmaf(h21, wsa.y, fmaf(h28, wsb.x, fmaf(h29, wsb.y, sp2))));
            sp3 = fmaf(h30, wsa.x, fmaf(h31, wsa.y, fmaf(h38, wsb.x, fmaf(h39, wsb.y, sp3))));
            af0[kt][0] = packh(h00, h01);
            af0[kt][1] = packh(h10, h11);
            af0[kt][2] = packh(h08, h09);
            af0[kt][3] = packh(h18, h19);
            af1[kt][0] = packh(h20, h21);
            af1[kt][1] = packh(h30, h31);
            af1[kt][2] = packh(h28, h29);
            af1[kt][3] = packh(h38, h39);
        }
        // sigma-dot quad reduce
        sp0 += __shfl_xor_sync(0xffffffffu, sp0, 1);
        sp0 += __shfl_xor_sync(0xffffffffu, sp0, 2);
        sp1 += __shfl_xor_sync(0xffffffffu, sp1, 1);
        sp1 += __shfl_xor_sync(0xffffffffu, sp1, 2);
        sp2 += __shfl_xor_sync(0xffffffffu, sp2, 1);
        sp2 += __shfl_xor_sync(0xffffffffu, sp2, 2);
        sp3 += __shfl_xor_sync(0xffffffffu, sp3, 1);
        sp3 += __shfl_xor_sync(0xffffffffu, sp3, 2);
        if (tq == 0) { sigb[r0] = sp0; sigb[r1] = sp1; sigb[r2] = sp2; sigb[r3] = sp3; }

        float a00 = 0.0f, a01 = 0.0f, a02 = 0.0f;   // tile0 row r0
        float a10 = 0.0f, a11 = 0.0f, a12 = 0.0f;   // tile0 row r1
        float a20 = 0.0f, a21 = 0.0f, a22 = 0.0f;   // tile1 row r2
        float a30 = 0.0f, a31 = 0.0f, a32 = 0.0f;   // tile1 row r3
        #pragma unroll
        for (int ntp = 0; ntp < 4; ntp++) {
            // D partials: [tile][nt-in-pair]
            float e00 = 0.0f, e01 = 0.0f, e02 = 0.0f, e03 = 0.0f;  // tile0, ntEven
            float e10 = 0.0f, e11 = 0.0f, e12 = 0.0f, e13 = 0.0f;  // tile0, ntOdd
            float e20 = 0.0f, e21 = 0.0f, e22 = 0.0f, e23 = 0.0f;  // tile1, ntEven
            float e30 = 0.0f, e31 = 0.0f, e32 = 0.0f, e33 = 0.0f;  // tile1, ntOdd
            const uint4* bnt = bp + ntp * 256 + lid;
            #pragma unroll
            for (int kt = 0; kt < 8; kt++) {
                uint4 b = bnt[kt * 32];
                mma_f16(e00, e01, e02, e03, af0[kt][0], af0[kt][1], af0[kt][2], af0[kt][3], b.x, b.y);
                mma_f16(e10, e11, e12, e13, af0[kt][0], af0[kt][1], af0[kt][2], af0[kt][3], b.z, b.w);
                mma_f16(e20, e21, e22, e23, af1[kt][0], af1[kt][1], af1[kt][2], af1[kt][3], b.x, b.y);
                mma_f16(e30, e31, e32, e33, af1[kt][0], af1[kt][1], af1[kt][2], af1[kt][3], b.z, b.w);
            }
            // epilogue fold: ntEven cols cE = 16ntp+2tq, ntOdd cols cO = cE+8
            const int cE = ntp * 16 + 2 * tq;
            const int cO = cE + 8;
            float4 wEa = qrw2[cE], wEb = qrw2[cE + 1];
            float4 wOa = qrw2[cO], wOb = qrw2[cO + 1];
            // tile0 row r0
            float h;
            h = fmaxf(e00 + wEa.w, 0.0f); a00 = fmaf(h, wEa.x, a00); a01 = fmaf(h, wEa.y, a01); a02 = fmaf(h, wEa.z, a02);
            h = fmaxf(e01 + wEb.w, 0.0f); a00 = fmaf(h, wEb.x, a00); a01 = fmaf(h, wEb.y, a01); a02 = fmaf(h, wEb.z, a02);
            h = fmaxf(e10 + wOa.w, 0.0f); a00 = fmaf(h, wOa.x, a00); a01 = fmaf(h, wOa.y, a01); a02 = fmaf(h, wOa.z, a02);
            h = fmaxf(e11 + wOb.w, 0.0f); a00 = fmaf(h, wOb.x, a00); a01 = fmaf(h, wOb.y, a01); a02 = fmaf(h, wOb.z, a02);
            // tile0 row r1
            h = fmaxf(e02 + wEa.w, 0.0f); a10 = fmaf(h, wEa.x, a10); a11 = fmaf(h, wEa.y, a11); a12 = fmaf(h, wEa.z, a12);
            h = fmaxf(e03 + wEb.w, 0.0f); a10 = fmaf(h, wEb.x, a10); a11 = fmaf(h, wEb.y, a11); a12 = fmaf(h, wEb.z, a12);
            h = fmaxf(e12 + wOa.w, 0.0f); a10 = fmaf(h, wOa.x, a10); a11 = fmaf(h, wOa.y, a11); a12 = fmaf(h, wOa.z, a12);
            h = fmaxf(e13 + wOb.w, 0.0f); a10 = fmaf(h, wOb.x, a10); a11 = fmaf(h, wOb.y, a11); a12 = fmaf(h, wOb.z, a12);
            // tile1 row r2
            h = fmaxf(e20 + wEa.w, 0.0f); a20 = fmaf(h, wEa.x, a20); a21 = fmaf(h, wEa.y, a21); a22 = fmaf(h, wEa.z, a22);
            h = fmaxf(e21 + wEb.w, 0.0f); a20 = fmaf(h, wEb.x, a20); a21 = fmaf(h, wEb.y, a21); a22 = fmaf(h, wEb.z, a22);
            h = fmaxf(e30 + wOa.w, 0.0f); a20 = fmaf(h, wOa.x, a20); a21 = fmaf(h, wOa.y, a21); a22 = fmaf(h, wOa.z, a22);
            h = fmaxf(e31 + wOb.w, 0.0f); a20 = fmaf(h, wOb.x, a20); a21 = fmaf(h, wOb.y, a21); a22 = fmaf(h, wOb.z, a22);
            // tile1 row r3
            h = fmaxf(e22 + wEa.w, 0.0f); a30 = fmaf(h, wEa.x, a30); a31 = fmaf(h, wEa.y, a31); a32 = fmaf(h, wEa.z, a32);
            h = fmaxf(e23 + wEb.w, 0.0f); a30 = fmaf(h, wEb.x, a30); a31 = fmaf(h, wEb.y, a31); a32 = fmaf(h, wEb.z, a32);
            h = fmaxf(e32 + wOa.w, 0.0f); a30 = fmaf(h, wOa.x, a30); a31 = fmaf(h, wOa.y, a31); a32 = fmaf(h, wOa.z, a32);
            h = fmaxf(e33 + wOb.w, 0.0f); a30 = fmaf(h, wOb.x, a30); a31 = fmaf(h, wOb.y, a31); a32 = fmaf(h, wOb.z, a32);
        }
        // quad reduce
        #pragma unroll
        for (int d = 1; d <= 2; d <<= 1) {
            a00 += __shfl_xor_sync(0xffffffffu, a00, d);
            a01 += __shfl_xor_sync(0xffffffffu, a01, d);
            a02 += __shfl_xor_sync(0xffffffffu, a02, d);
            a10 += __shfl_xor_sync(0xffffffffu, a10, d);
            a11 += __shfl_xor_sync(0xffffffffu, a11, d);
            a12 += __shfl_xor_sync(0xffffffffu, a12, d);
            a20 += __shfl_xor_sync(0xffffffffu, a20, d);
            a21 += __shfl_xor_sync(0xffffffffu, a21, d);
            a22 += __shfl_xor_sync(0xffffffffu, a22, d);
            a30 += __shfl_xor_sync(0xffffffffu, a30, d);
            a31 += __shfl_xor_sync(0xffffffffu, a31, d);
            a32 += __shfl_xor_sync(0xffffffffu, a32, d);
        }
        if (tq == 0) {
            rgbb[r0] = make_float4(1.0f / (1.0f + expf(-(a00 + rb0))),
                                   1.0f / (1.0f + expf(-(a01 + rb1))),
                                   1.0f / (1.0f + expf(-(a02 + rb2v))), 0.0f);
            rgbb[r1] = make_float4(1.0f / (1.0f + expf(-(a10 + rb0))),
                                   1.0f / (1.0f + expf(-(a11 + rb1))),
                                   1.0f / (1.0f + expf(-(a12 + rb2v))), 0.0f);
            rgbb[r2] = make_float4(1.0f / (1.0f + expf(-(a20 + rb0))),
                                   1.0f / (1.0f + expf(-(a21 + rb1))),
                                   1.0f / (1.0f + expf(-(a22 + rb2v))), 0.0f);
            rgbb[r3] = make_float4(1.0f / (1.0f + expf(-(a30 + rb0))),
                                   1.0f / (1.0f + expf(-(a31 + rb1))),
                                   1.0f / (1.0f + expf(-(a32 + rb2v))), 0.0f);
        }
    }
    __syncthreads();

    // ========== PHASE B: scan + weighted accumulation ========================
    float rgb0, rgb1, rgb2;
    {
        float tA  = tmap((float)tid * USTEP);
        float tA1 = tmap((float)(tid + 1) * USTEP);
        float tB  = tmap((float)(tid + 128) * USTEP);
        float tB1 = tmap((float)(tid + 129) * USTEP);
        float distA = tA1 - tA, distB = tB1 - tB;

        float preA = sigb[tid] + sconst;
        float preB = sigb[tid + 128] + sconst;
        float sigmaA = mA ? ((preA > 20.0f) ? preA : log1pf(expf(preA))) : 0.0f;
        float sigmaB = mB ? ((preB > 20.0f) ? preB : log1pf(expf(preB))) : 0.0f;

        float aA = -sigmaA * distA;
        float aB = -sigmaB * distB;
        float incA = aA, incB = aB;
        #pragma unroll
        for (int off = 1; off < 32; off <<= 1) {
            float yA = __shfl_up_sync(0xffffffffu, incA, off);
            float yB = __shfl_up_sync(0xffffffffu, incB, off);
            if (lid >= off) { incA += yA; incB += yB; }
        }
        if (lid == 31) { wsumA[wid] = incA; wsumB[wid] = incB; }
        __syncthreads();
        float offA = 0.0f, offB = 0.0f, totalA = 0.0f;
        #pragma unroll
        for (int i = 0; i < 4; i++) {
            float vA = wsumA[i];
            totalA += vA;
            if (i < wid) { offA += vA; offB += wsumB[i]; }
        }
        float exclA = offA + incA - aA;
        float exclB = totalA + offB + incB - aB;
        float transA = expf(exclA), transB = expf(exclB);
        float weightA = transA * (1.0f - expf(aA));
        float weightB = transB * (1.0f - expf(aB));
        float wA = (mA && transA > EARLY_TERM) ? weightA : 0.0f;
        float wB = (mB && transB > EARLY_TERM) ? weightB : 0.0f;

        float4 cA = rgbb[tid];
        float4 cB = rgbb[tid + 128];
        rgb0 = wA * cA.x + wB * cB.x;
        rgb1 = wA * cA.y + wB * cB.y;
        rgb2 = wA * cA.z + wB * cB.z;
    }

    // ---- deterministic block reduction ----
    #pragma unroll
    for (int off = 16; off > 0; off >>= 1) {
        rgb0 += __shfl_down_sync(0xffffffffu, rgb0, off);
        rgb1 += __shfl_down_sync(0xffffffffu, rgb1, off);
        rgb2 += __shfl_down_sync(0xffffffffu, rgb2, off);
    }
    if (lid == 0) { wred[wid][0] = rgb0; wred[wid][1] = rgb1; wred[wid][2] = rgb2; }
    __syncthreads();
    if (tid < 3) {
        float s = 0.0f;
        #pragma unroll
        for (int w = 0; w < 4; w++) s += wred[w][tid];
        out[ray * 3 + tid] = s;
    }
}

extern "C" void kernel_launch(void* const* d_in, const int* in_sizes, int n_in,
                              void* d_out, int out_size) {
    const float* rays_o = (const float*)d_in[0];
    const float* rays_d = (const float*)d_in[1];
    const float* grid   = (const float*)d_in[2];
    const float* f_w1   = (const float*)d_in[3];
    const float* f_b1   = (const float*)d_in[4];
    const float* f_w2   = (const float*)d_in[5];
    const float* f_b2   = (const float*)d_in[6];
    const float* s_w    = (const float*)d_in[7];
    const float* s_b    = (const float*)d_in[8];
    const float* r_w1   = (const float*)d_in[9];
    const float* r_b1   = (const float*)d_in[10];
    const float* r_w2   = (const float*)d_in[11];
    const float* r_b2   = (const float*)d_in[12];
    float* out = (float*)d_out;

    const int n_rays = in_sizes[0] / 3;

    prep_kernel<<<(2241 + 255) / 256, 256>>>(f_w2, f_b2, s_w, s_b, r_w1, r_b1);

    cudaFuncSetAttribute(nerf_render_kernel,
                         cudaFuncAttributeMaxDynamicSharedMemorySize, SMEM_BYTES);
    nerf_render_kernel<<<n_rays, 128, SMEM_BYTES>>>(
        rays_o, rays_d, grid, f_w1, f_b1, r_w1, r_w2, r_b2, out);
}

// round 13
// speedup vs baseline: 2.0274x; 1.2021x over previous
#include <cuda_runtime.h>
#include <cuda_fp16.h>
#include <math.h>

typedef unsigned int u32;

#define OPACITY_TH 0.01f
#define EARLY_TERM 1e-4f

// pack two floats to f16x2: low16 = f16(lo_f), high16 = f16(hi_f)
__device__ __forceinline__ u32 packh(float lo_f, float hi_f) {
    __half2 h = __halves2half2(__float2half_rn(lo_f), __float2half_rn(hi_f));
    return *reinterpret_cast<u32*>(&h);
}
__device__ __forceinline__ float2 unpackh(u32 v) {
    __half2 h = *reinterpret_cast<__half2*>(&v);
    return __half22float2(h);
}

__device__ __forceinline__ void mma_f16(float& d0, float& d1, float& d2, float& d3,
                                        u32 a0, u32 a1, u32 a2, u32 a3,
                                        u32 b0, u32 b1) {
    asm volatile("mma.sync.aligned.m16n8k16.row.col.f32.f16.f16.f32 "
        "{%0,%1,%2,%3}, {%4,%5,%6,%7}, {%8,%9}, {%0,%1,%2,%3};"
        : "+f"(d0), "+f"(d1), "+f"(d2), "+f"(d3)
        : "r"(a0), "r"(a1), "r"(a2), "r"(a3), "r"(b0), "r"(b1));
}

// ---------------- precomputed globals (prep kernel output) ----------------
// Layer-2 B fragments (fp16), nt-paired (see R12 layout)
__device__ __align__(16) u32 g_Bq[4096];
// Layer-1 B fragments, ntile-paired: uint4[j*32+lane] = {nt2j.b0, nt2j.b1, nt2j1.b0, nt2j1.b1}
//   b0 (k=2tq,2tq+1): tq0=(Wx_hi,Wy_hi) tq1=(Wz_hi,b_hi) tq2=(Wx_hi,Wy_hi) tq3=(Wz_hi,b_lo)
//   b1 (k+8):         tq0=(Wx_lo,Wy_lo) tq1=(Wz_lo,0)    tq2=0             tq3=0
__device__ __align__(16) uint4 g_B1q[256];
__device__ float g_ws[128];      // f_w2[k,:]·s_w
__device__ float g_hconst[64];   // f_b2 @ r_w1[:64,:] + r_b1
__device__ float g_sconst[1];    // f_b2·s_w + s_b

__global__ void prep_kernel(const float* __restrict__ f_w1, const float* __restrict__ f_b1,
                            const float* __restrict__ f_w2, const float* __restrict__ f_b2,
                            const float* __restrict__ s_w,  const float* __restrict__ s_b,
                            const float* __restrict__ r_w1, const float* __restrict__ r_b1)
{
    int i = blockIdx.x * blockDim.x + threadIdx.x;
    if (i < 2048) {
        int fid = i >> 5, lane = i & 31;
        int nt = fid >> 3, kt = fid & 7;
        int n = nt * 8 + (lane >> 2);
        int tq = lane & 3;
        int k0 = kt * 16 + 2 * tq;
        float v[4];
        #pragma unroll
        for (int e = 0; e < 4; e++) {
            int k = k0 + (e >> 1) * 8 + (e & 1);
            float s = 0.0f;
            #pragma unroll 8
            for (int t = 0; t < 64; t++) s += f_w2[k * 64 + t] * r_w1[t * 64 + n];
            v[e] = s;
        }
        int ntp = nt >> 1;
        int base = ((ntp * 8 + kt) * 32 + lane) * 4 + (nt & 1) * 2;
        g_Bq[base + 0] = packh(v[0], v[1]);
        g_Bq[base + 1] = packh(v[2], v[3]);
    } else if (i < 2304) {
        // layer-1 B fragments
        int ii = i - 2048;
        int j = ii >> 5, lane = ii & 31;
        int tq = lane & 3;
        u32 r[4];
        #pragma unroll
        for (int half = 0; half < 2; half++) {
            int nt = 2 * j + half;
            int n = nt * 8 + (lane >> 2);
            float wx = f_w1[0 * 128 + n], wy = f_w1[1 * 128 + n], wz = f_w1[2 * 128 + n];
            float bb = f_b1[n];
            float2 hxy = unpackh(packh(wx, wy));
            float2 hzb = unpackh(packh(wz, bb));
            float lwx = wx - hxy.x, lwy = wy - hxy.y;
            float lwz = wz - hzb.x, lbb = bb - hzb.y;
            u32 b0, b1;
            if (tq == 0)      { b0 = packh(wx, wy);  b1 = packh(lwx, lwy); }
            else if (tq == 1) { b0 = packh(wz, bb);  b1 = packh(lwz, 0.0f); }
            else if (tq == 2) { b0 = packh(wx, wy);  b1 = 0u; }
            else              { b0 = packh(wz, lbb); b1 = 0u; }
            r[2 * half] = b0; r[2 * half + 1] = b1;
        }
        g_B1q[j * 32 + lane] = make_uint4(r[0], r[1], r[2], r[3]);
    } else if (i < 2432) {
        int k = i - 2304;
        float s = 0.0f;
        #pragma unroll 8
        for (int t = 0; t < 64; t++) s += f_w2[k * 64 + t] * s_w[t];
        g_ws[k] = s;
    } else if (i < 2496) {
        int j = i - 2432;
        float s = r_b1[j];
        #pragma unroll 8
        for (int t = 0; t < 64; t++) s += f_b2[t] * r_w1[t * 64 + j];
        g_hconst[j] = s;
    } else if (i == 2496) {
        float s = s_b[0];
        for (int t = 0; t < 64; t++) s += f_b2[t] * s_w[t];
        g_sconst[0] = s;
    }
}

// ---------------- dynamic shared layout (bytes) ----------------
#define SM_BQ    0        // 16KB layer-2 B
#define SM_B1    16384    // 4KB layer-1 B (uint4[256])
#define SM_WS    20480    // 512B
#define SM_RW2   20992    // [64][4] 1KB
#define SM_SIGB  22016    // sigma_pre[256] 1KB
#define SM_RGBB  23040    // rgbRaw[256] float4 4KB
#define SM_POS   27136    // positions[256] float4 4KB
#define SM_MISC  31232    // [0..2]=r_b2, [3]=sconst
#define SMEM_BYTES 31248

__device__ __forceinline__ float tmap(float u) {
    return (u < 0.5f) ? 2.0f * u : 1.0f / (2.0f - 2.0f * u);
}

#define USTEP ((257.0f / 258.0f) / 256.0f)

__device__ __forceinline__ void ray_pos(int s, float ox, float oy, float oz,
                                        float dx, float dy, float dz,
                                        float& px, float& py, float& pz) {
    float tv = tmap((float)s * USTEP);
    px = ox + dx * tv; py = oy + dy * tv; pz = oz + dz * tv;
    float nrm = sqrtf(px * px + py * py + pz * pz);
    float cs = (nrm <= 1.0f) ? 0.5f : (2.0f - 1.0f / nrm) / nrm * 0.5f;
    px *= cs; py *= cs; pz *= cs;
}

__device__ __forceinline__ float sample_grid(const float* __restrict__ grid,
                                             float px, float py, float pz) {
    float ixf = ((px + 1.0f) * 128.0f - 1.0f) * 0.5f;
    float iyf = ((py + 1.0f) * 128.0f - 1.0f) * 0.5f;
    float izf = ((pz + 1.0f) * 128.0f - 1.0f) * 0.5f;
    float fx0 = floorf(ixf), fy0 = floorf(iyf), fz0 = floorf(izf);
    int ix0 = (int)fx0, iy0 = (int)fy0, iz0 = (int)fz0;
    float fx = ixf - fx0, fy = iyf - fy0, fz = izf - fz0;
    float occ = 0.0f;
    #pragma unroll
    for (int dzc = 0; dzc < 2; dzc++) {
        int cz = iz0 + dzc;
        if (cz < 0 || cz >= 128) continue;
        float wz = dzc ? fz : 1.0f - fz;
        #pragma unroll
        for (int dyc = 0; dyc < 2; dyc++) {
            int cy = iy0 + dyc;
            if (cy < 0 || cy >= 128) continue;
            float wy = dyc ? fy : 1.0f - fy;
            #pragma unroll
            for (int dxc = 0; dxc < 2; dxc++) {
                int cx = ix0 + dxc;
                if (cx < 0 || cx >= 128) continue;
                float wx = dxc ? fx : 1.0f - fx;
                occ += wz * wy * wx * __ldg(&grid[(cz << 14) + (cy << 7) + cx]);
            }
        }
    }
    return occ;
}

// Build layer-1 A fragments for one row (contracted position P).
// aL = k-lo fragment (k 2tq..): tq0=(px,py)hi tq1=(pz,1)hi tq2=(px,py)lo tq3=(pz,1)lo
// aH = k-hi fragment (k 8+2tq..): tq0=(px,py)hi tq1=(pz,0)hi tq2,3=0
__device__ __forceinline__ void build_a1(float4 P, int tq, u32& aL, u32& aH) {
    u32 c0 = packh(P.x, P.y);
    u32 c1 = packh(P.z, 1.0f);
    float2 fxy = unpackh(c0);
    float2 fz1 = unpackh(c1);
    u32 c2 = packh(P.x - fxy.x, P.y - fxy.y);
    u32 c3 = packh(P.z - fz1.x, 1.0f);
    aL = (tq < 2) ? ((tq == 1) ? c1 : c0) : ((tq == 3) ? c3 : c2);
    aH = (tq == 0) ? c0 : ((tq == 1) ? (c1 & 0xFFFFu) : 0u);
}

__global__ void __launch_bounds__(128, 4) nerf_render_kernel(
    const float* __restrict__ rays_o, const float* __restrict__ rays_d,
    const float* __restrict__ grid,
    const float* __restrict__ r_w1, const float* __restrict__ r_w2,
    const float* __restrict__ r_b2,
    float* __restrict__ out)
{
    extern __shared__ __align__(16) char smdyn[];
    __shared__ float wsumA[4], wsumB[4];
    __shared__ float wred[4][3];

    const int tid = threadIdx.x;
    const int wid = tid >> 5;
    const int lid = tid & 31;
    const int g   = lid >> 2;
    const int tq  = lid & 3;
    const int ray = blockIdx.x;

    const float ox = __ldg(&rays_o[ray * 3 + 0]);
    const float oy = __ldg(&rays_o[ray * 3 + 1]);
    const float oz = __ldg(&rays_o[ray * 3 + 2]);
    const float dx = __ldg(&rays_d[ray * 3 + 0]);
    const float dy = __ldg(&rays_d[ray * 3 + 1]);
    const float dz = __ldg(&rays_d[ray * 3 + 2]);

    float4* posb = (float4*)(smdyn + SM_POS);

    // ---- EARLY: positions + occupancy masks (LDGs hidden behind staging) ----
    bool mA, mB;
    {
        float pxA, pyA, pzA, pxB, pyB, pzB;
        ray_pos(tid, ox, oy, oz, dx, dy, dz, pxA, pyA, pzA);
        ray_pos(tid + 128, ox, oy, oz, dx, dy, dz, pxB, pyB, pzB);
        posb[tid]       = make_float4(pxA, pyA, pzA, 0.0f);
        posb[tid + 128] = make_float4(pxB, pyB, pzB, 0.0f);
        mA = sample_grid(grid, pxA, pyA, pzA) > OPACITY_TH;
        mB = sample_grid(grid, pxB, pyB, pzB) > OPACITY_TH;
    }

    // ---- staging ----
    {
        uint4* dstB = (uint4*)(smdyn + SM_BQ);
        const uint4* srcB = (const uint4*)g_Bq;
        #pragma unroll
        for (int i = 0; i < 8; i++) dstB[tid + 128 * i] = srcB[tid + 128 * i];
        uint4* dstB1 = (uint4*)(smdyn + SM_B1);
        #pragma unroll
        for (int i = 0; i < 2; i++) dstB1[tid + 128 * i] = g_B1q[tid + 128 * i];
        ((float*)(smdyn + SM_WS))[tid] = g_ws[tid];
        if (tid < 64) {
            float hcv = g_hconst[tid]
                      + dx * r_w1[64 * 64 + tid]
                      + dy * r_w1[65 * 64 + tid]
                      + dz * r_w1[66 * 64 + tid];
            *(float4*)(smdyn + SM_RW2 + tid * 16) =
                make_float4(r_w2[tid * 3], r_w2[tid * 3 + 1], r_w2[tid * 3 + 2], hcv);
        }
        if (tid < 3)  ((float*)(smdyn + SM_MISC))[tid] = r_b2[tid];
        if (tid == 3) ((float*)(smdyn + SM_MISC))[3] = g_sconst[0];
    }
    __syncthreads();

    const float*  wsf  = (const float*)(smdyn + SM_WS);
    const uint4*  bp   = (const uint4*)(smdyn + SM_BQ);
    const uint4*  b1p  = (const uint4*)(smdyn + SM_B1);
    const float4* qrw2 = (const float4*)(smdyn + SM_RW2);
    float*        sigb = (float*)(smdyn + SM_SIGB);
    float4*       rgbb = (float4*)(smdyn + SM_RGBB);
    const float4* posv = (const float4*)(smdyn + SM_POS);
    const float rb0  = ((const float*)(smdyn + SM_MISC))[0];
    const float rb1  = ((const float*)(smdyn + SM_MISC))[1];
    const float rb2v = ((const float*)(smdyn + SM_MISC))[2];
    const float sconst = ((const float*)(smdyn + SM_MISC))[3];

    // ========== PHASE A: layer-1 MMA -> layer-2 MMA, 2 M-tiles per pass ======
    #pragma unroll
    for (int mtp = 0; mtp < 2; mtp++) {
        const int tt0 = wid * 4 + 2 * mtp;
        const int r0 = 16 * tt0 + g;
        const int r1 = r0 + 8;
        const int r2 = r0 + 16;
        const int r3 = r0 + 24;

        // layer-1 A fragments for 4 rows
        u32 aL0, aH0, aL1, aH1, aL2, aH2, aL3, aH3;
        build_a1(posv[r0], tq, aL0, aH0);
        build_a1(posv[r1], tq, aL1, aH1);
        build_a1(posv[r2], tq, aL2, aH2);
        build_a1(posv[r3], tq, aL3, aH3);

        // layer-1 MMAs: produce h (fp32), relu, sigma-dot, pack layer-2 A frags
        u32 af0[8][4], af1[8][4];
        float sp0 = 0.0f, sp1 = 0.0f, sp2 = 0.0f, sp3 = 0.0f;
        #pragma unroll
        for (int j = 0; j < 8; j++) {
            uint4 b = b1p[j * 32 + lid];
            float e0 = 0.0f, e1 = 0.0f, e2 = 0.0f, e3 = 0.0f;   // tile0 nt2j
            float f0 = 0.0f, f1 = 0.0f, f2 = 0.0f, f3 = 0.0f;   // tile0 nt2j+1
            float q0 = 0.0f, q1 = 0.0f, q2 = 0.0f, q3 = 0.0f;   // tile1 nt2j
            float s0 = 0.0f, s1 = 0.0f, s2 = 0.0f, s3 = 0.0f;   // tile1 nt2j+1
            mma_f16(e0, e1, e2, e3, aL0, aL1, aH0, aH1, b.x, b.y);
            mma_f16(f0, f1, f2, f3, aL0, aL1, aH0, aH1, b.z, b.w);
            mma_f16(q0, q1, q2, q3, aL2, aL3, aH2, aH3, b.x, b.y);
            mma_f16(s0, s1, s2, s3, aL2, aL3, aH2, aH3, b.z, b.w);
            e0 = fmaxf(e0, 0.0f); e1 = fmaxf(e1, 0.0f); e2 = fmaxf(e2, 0.0f); e3 = fmaxf(e3, 0.0f);
            f0 = fmaxf(f0, 0.0f); f1 = fmaxf(f1, 0.0f); f2 = fmaxf(f2, 0.0f); f3 = fmaxf(f3, 0.0f);
            q0 = fmaxf(q0, 0.0f); q1 = fmaxf(q1, 0.0f); q2 = fmaxf(q2, 0.0f); q3 = fmaxf(q3, 0.0f);
            s0 = fmaxf(s0, 0.0f); s1 = fmaxf(s1, 0.0f); s2 = fmaxf(s2, 0.0f); s3 = fmaxf(s3, 0.0f);
            const int k0 = j * 16 + 2 * tq;
            float2 wsa = *(const float2*)&wsf[k0];
            float2 wsb = *(const float2*)&wsf[k0 + 8];
            sp0 = fmaf(e0, wsa.x, fmaf(e1, wsa.y, fmaf(f0, wsb.x, fmaf(f1, wsb.y, sp0))));
            sp1 = fmaf(e2, wsa.x, fmaf(e3, wsa.y, fmaf(f2, wsb.x, fmaf(f3, wsb.y, sp1))));
            sp2 = fmaf(q0, wsa.x, fmaf(q1, wsa.y, fmaf(s0, wsb.x, fmaf(s1, wsb.y, sp2))));
            sp3 = fmaf(q2, wsa.x, fmaf(q3, wsa.y, fmaf(s2, wsb.x, fmaf(s3, wsb.y, sp3))));
            af0[j][0] = packh(e0, e1);
            af0[j][1] = packh(e2, e3);
            af0[j][2] = packh(f0, f1);
            af0[j][3] = packh(f2, f3);
            af1[j][0] = packh(q0, q1);
            af1[j][1] = packh(q2, q3);
            af1[j][2] = packh(s0, s1);
            af1[j][3] = packh(s2, s3);
        }
        // sigma-dot quad reduce
        sp0 += __shfl_xor_sync(0xffffffffu, sp0, 1);
        sp0 += __shfl_xor_sync(0xffffffffu, sp0, 2);
        sp1 += __shfl_xor_sync(0xffffffffu, sp1, 1);
        sp1 += __shfl_xor_sync(0xffffffffu, sp1, 2);
        sp2 += __shfl_xor_sync(0xffffffffu, sp2, 1);
        sp2 += __shfl_xor_sync(0xffffffffu, sp2, 2);
        sp3 += __shfl_xor_sync(0xffffffffu, sp3, 1);
        sp3 += __shfl_xor_sync(0xffffffffu, sp3, 2);
        if (tq == 0) { sigb[r0] = sp0; sigb[r1] = sp1; sigb[r2] = sp2; sigb[r3] = sp3; }

        // layer-2: 4 ntile-pairs x 8 kt
        float a00 = 0.0f, a01 = 0.0f, a02 = 0.0f;
        float a10 = 0.0f, a11 = 0.0f, a12 = 0.0f;
        float a20 = 0.0f, a21 = 0.0f, a22 = 0.0f;
        float a30 = 0.0f, a31 = 0.0f, a32 = 0.0f;
        #pragma unroll
        for (int ntp = 0; ntp < 4; ntp++) {
            float e00 = 0.0f, e01 = 0.0f, e02 = 0.0f, e03 = 0.0f;
            float e10 = 0.0f, e11 = 0.0f, e12 = 0.0f, e13 = 0.0f;
            float e20 = 0.0f, e21 = 0.0f, e22 = 0.0f, e23 = 0.0f;
            float e30 = 0.0f, e31 = 0.0f, e32 = 0.0f, e33 = 0.0f;
            const uint4* bnt = bp + ntp * 256 + lid;
            #pragma unroll
            for (int kt = 0; kt < 8; kt++) {
                uint4 b = bnt[kt * 32];
                mma_f16(e00, e01, e02, e03, af0[kt][0], af0[kt][1], af0[kt][2], af0[kt][3], b.x, b.y);
                mma_f16(e10, e11, e12, e13, af0[kt][0], af0[kt][1], af0[kt][2], af0[kt][3], b.z, b.w);
                mma_f16(e20, e21, e22, e23, af1[kt][0], af1[kt][1], af1[kt][2], af1[kt][3], b.x, b.y);
                mma_f16(e30, e31, e32, e33, af1[kt][0], af1[kt][1], af1[kt][2], af1[kt][3], b.z, b.w);
            }
            const int cE = ntp * 16 + 2 * tq;
            const int cO = cE + 8;
            float4 wEa = qrw2[cE], wEb = qrw2[cE + 1];
            float4 wOa = qrw2[cO], wOb = qrw2[cO + 1];
            float h;
            h = fmaxf(e00 + wEa.w, 0.0f); a00 = fmaf(h, wEa.x, a00); a01 = fmaf(h, wEa.y, a01); a02 = fmaf(h, wEa.z, a02);
            h = fmaxf(e01 + wEb.w, 0.0f); a00 = fmaf(h, wEb.x, a00); a01 = fmaf(h, wEb.y, a01); a02 = fmaf(h, wEb.z, a02);
            h = fmaxf(e10 + wOa.w, 0.0f); a00 = fmaf(h, wOa.x, a00); a01 = fmaf(h, wOa.y, a01); a02 = fmaf(h, wOa.z, a02);
            h = fmaxf(e11 + wOb.w, 0.0f); a00 = fmaf(h, wOb.x, a00); a01 = fmaf(h, wOb.y, a01); a02 = fmaf(h, wOb.z, a02);
            h = fmaxf(e02 + wEa.w, 0.0f); a10 = fmaf(h, wEa.x, a10); a11 = fmaf(h, wEa.y, a11); a12 = fmaf(h, wEa.z, a12);
            h = fmaxf(e03 + wEb.w, 0.0f); a10 = fmaf(h, wEb.x, a10); a11 = fmaf(h, wEb.y, a11); a12 = fmaf(h, wEb.z, a12);
            h = fmaxf(e12 + wOa.w, 0.0f); a10 = fmaf(h, wOa.x, a10); a11 = fmaf(h, wOa.y, a11); a12 = fmaf(h, wOa.z, a12);
            h = fmaxf(e13 + wOb.w, 0.0f); a10 = fmaf(h, wOb.x, a10); a11 = fmaf(h, wOb.y, a11); a12 = fmaf(h, wOb.z, a12);
            h = fmaxf(e20 + wEa.w, 0.0f); a20 = fmaf(h, wEa.x, a20); a21 = fmaf(h, wEa.y, a21); a22 = fmaf(h, wEa.z, a22);
            h = fmaxf(e21 + wEb.w, 0.0f); a20 = fmaf(h, wEb.x, a20); a21 = fmaf(h, wEb.y, a21); a22 = fmaf(h, wEb.z, a22);
            h = fmaxf(e30 + wOa.w, 0.0f); a20 = fmaf(h, wOa.x, a20); a21 = fmaf(h, wOa.y, a21); a22 = fmaf(h, wOa.z, a22);
            h = fmaxf(e31 + wOb.w, 0.0f); a20 = fmaf(h, wOb.x, a20); a21 = fmaf(h, wOb.y, a21); a22 = fmaf(h, wOb.z, a22);
            h = fmaxf(e22 + wEa.w, 0.0f); a30 = fmaf(h, wEa.x, a30); a31 = fmaf(h, wEa.y, a31); a32 = fmaf(h, wEa.z, a32);
            h = fmaxf(e23 + wEb.w, 0.0f); a30 = fmaf(h, wEb.x, a30); a31 = fmaf(h, wEb.y, a31); a32 = fmaf(h, wEb.z, a32);
            h = fmaxf(e32 + wOa.w, 0.0f); a30 = fmaf(h, wOa.x, a30); a31 = fmaf(h, wOa.y, a31); a32 = fmaf(h, wOa.z, a32);
            h = fmaxf(e33 + wOb.w, 0.0f); a30 = fmaf(h, wOb.x, a30); a31 = fmaf(h, wOb.y, a31); a32 = fmaf(h, wOb.z, a32);
        }
        #pragma unroll
        for (int d = 1; d <= 2; d <<= 1) {
            a00 += __shfl_xor_sync(0xffffffffu, a00, d);
            a01 += __shfl_xor_sync(0xffffffffu, a01, d);
            a02 += __shfl_xor_sync(0xffffffffu, a02, d);
            a10 += __shfl_xor_sync(0xffffffffu, a10, d);
            a11 += __shfl_xor_sync(0xffffffffu, a11, d);
            a12 += __shfl_xor_sync(0xffffffffu, a12, d);
            a20 += __shfl_xor_sync(0xffffffffu, a20, d);
            a21 += __shfl_xor_sync(0xffffffffu, a21, d);
            a22 += __shfl_xor_sync(0xffffffffu, a22, d);
            a30 += __shfl_xor_sync(0xffffffffu, a30, d);
            a31 += __shfl_xor_sync(0xffffffffu, a31, d);
            a32 += __shfl_xor_sync(0xffffffffu, a32, d);
        }
        if (tq == 0) {
            rgbb[r0] = make_float4(1.0f / (1.0f + expf(-(a00 + rb0))),
                                   1.0f / (1.0f + expf(-(a01 + rb1))),
                                   1.0f / (1.0f + expf(-(a02 + rb2v))), 0.0f);
            rgbb[r1] = make_float4(1.0f / (1.0f + expf(-(a10 + rb0))),
                                   1.0f / (1.0f + expf(-(a11 + rb1))),
                                   1.0f / (1.0f + expf(-(a12 + rb2v))), 0.0f);
            rgbb[r2] = make_float4(1.0f / (1.0f + expf(-(a20 + rb0))),
                                   1.0f / (1.0f + expf(-(a21 + rb1))),
                                   1.0f / (1.0f + expf(-(a22 + rb2v))), 0.0f);
            rgbb[r3] = make_float4(1.0f / (1.0f + expf(-(a30 + rb0))),
                                   1.0f / (1.0f + expf(-(a31 + rb1))),
                                   1.0f / (1.0f + expf(-(a32 + rb2v))), 0.0f);
        }
    }
    __syncthreads();

    // ========== PHASE B: scan + weighted accumulation ========================
    float rgb0, rgb1, rgb2;
    {
        float tA  = tmap((float)tid * USTEP);
        float tA1 = tmap((float)(tid + 1) * USTEP);
        float tB  = tmap((float)(tid + 128) * USTEP);
        float tB1 = tmap((float)(tid + 129) * USTEP);
        float distA = tA1 - tA, distB = tB1 - tB;

        float preA = sigb[tid] + sconst;
        float preB = sigb[tid + 128] + sconst;
        float sigmaA = mA ? ((preA > 20.0f) ? preA : log1pf(expf(preA))) : 0.0f;
        float sigmaB = mB ? ((preB > 20.0f) ? preB : log1pf(expf(preB))) : 0.0f;

        float aA = -sigmaA * distA;
        float aB = -sigmaB * distB;
        float incA = aA, incB = aB;
        #pragma unroll
        for (int off = 1; off < 32; off <<= 1) {
            float yA = __shfl_up_sync(0xffffffffu, incA, off);
            float yB = __shfl_up_sync(0xffffffffu, incB, off);
            if (lid >= off) { incA += yA; incB += yB; }
        }
        if (lid == 31) { wsumA[wid] = incA; wsumB[wid] = incB; }
        __syncthreads();
        float offA = 0.0f, offB = 0.0f, totalA = 0.0f;
        #pragma unroll
        for (int i = 0; i < 4; i++) {
            float vA = wsumA[i];
            totalA += vA;
            if (i < wid) { offA += vA; offB += wsumB[i]; }
        }
        float exclA = offA + incA - aA;
        float exclB = totalA + offB + incB - aB;
        float transA = expf(exclA), transB = expf(exclB);
        float weightA = transA * (1.0f - expf(aA));
        float weightB = transB * (1.0f - expf(aB));
        float wA = (mA && transA > EARLY_TERM) ? weightA : 0.0f;
        float wB = (mB && transB > EARLY_TERM) ? weightB : 0.0f;

        float4 cA = rgbb[tid];
        float4 cB = rgbb[tid + 128];
        rgb0 = wA * cA.x + wB * cB.x;
        rgb1 = wA * cA.y + wB * cB.y;
        rgb2 = wA * cA.z + wB * cB.z;
    }

    // ---- deterministic block reduction ----
    #pragma unroll
    for (int off = 16; off > 0; off >>= 1) {
        rgb0 += __shfl_down_sync(0xffffffffu, rgb0, off);
        rgb1 += __shfl_down_sync(0xffffffffu, rgb1, off);
        rgb2 += __shfl_down_sync(0xffffffffu, rgb2, off);
    }
    if (lid == 0) { wred[wid][0] = rgb0; wred[wid][1] = rgb1; wred[wid][2] = rgb2; }
    __syncthreads();
    if (tid < 3) {
        float s = 0.0f;
        #pragma unroll
        for (int w = 0; w < 4; w++) s += wred[w][tid];
        out[ray * 3 + tid] = s;
    }
}

extern "C" void kernel_launch(void* const* d_in, const int* in_sizes, int n_in,
                              void* d_out, int out_size) {
    const float* rays_o = (const float*)d_in[0];
    const float* rays_d = (const float*)d_in[1];
    const float* grid   = (const float*)d_in[2];
    const float* f_w1   = (const float*)d_in[3];
    const float* f_b1   = (const float*)d_in[4];
    const float* f_w2   = (const float*)d_in[5];
    const float* f_b2   = (const float*)d_in[6];
    const float* s_w    = (const float*)d_in[7];
    const float* s_b    = (const float*)d_in[8];
    const float* r_w1   = (const float*)d_in[9];
    const float* r_b1   = (const float*)d_in[10];
    const float* r_w2   = (const float*)d_in[11];
    const float* r_b2   = (const float*)d_in[12];
    float* out = (float*)d_out;

    const int n_rays = in_sizes[0] / 3;

    prep_kernel<<<(2497 + 255) / 256, 256>>>(f_w1, f_b1, f_w2, f_b2, s_w, s_b, r_w1, r_b1);

    cudaFuncSetAttribute(nerf_render_kernel,
                         cudaFuncAttributeMaxDynamicSharedMemorySize, SMEM_BYTES);
    nerf_render_kernel<<<n_rays, 128, SMEM_BYTES>>>(
        rays_o, rays_d, grid, r_w1, r_w2, r_b2, out);
}

// round 14
// speedup vs baseline: 2.1906x; 1.0805x over previous
#include <cuda_runtime.h>
#include <cuda_fp16.h>
#include <math.h>

typedef unsigned int u32;

#define OPACITY_TH 0.01f
#define EARLY_TERM 1e-4f

// pack two floats to f16x2 in ONE instruction: low16 = f16(lo_f), high16 = f16(hi_f)
__device__ __forceinline__ u32 packh(float lo_f, float hi_f) {
    u32 r; asm("cvt.rn.f16x2.f32 %0, %1, %2;" : "=r"(r) : "f"(hi_f), "f"(lo_f)); return r;
}
__device__ __forceinline__ float2 unpackh(u32 v) {
    __half2 h = *reinterpret_cast<__half2*>(&v);
    return __half22float2(h);
}

__device__ __forceinline__ void mma_f16(float& d0, float& d1, float& d2, float& d3,
                                        u32 a0, u32 a1, u32 a2, u32 a3,
                                        u32 b0, u32 b1) {
    asm volatile("mma.sync.aligned.m16n8k16.row.col.f32.f16.f16.f32 "
        "{%0,%1,%2,%3}, {%4,%5,%6,%7}, {%8,%9}, {%0,%1,%2,%3};"
        : "+f"(d0), "+f"(d1), "+f"(d2), "+f"(d3)
        : "r"(a0), "r"(a1), "r"(a2), "r"(a3), "r"(b0), "r"(b1));
}

// ---------------- precomputed globals (prep kernel output) ----------------
__device__ __align__(16) u32 g_Bq[4096];     // layer-2 B, nt-paired (R12 layout)
__device__ __align__(16) uint4 g_B1q[256];   // layer-1 B (R13 layout)
__device__ __align__(8)  uint2 g_WsF[256];   // sigma B frags: col0=ws, cols1-7=0
__device__ float g_hconst[64];               // f_b2 @ r_w1[:64,:] + r_b1
__device__ float g_sconst[1];                // f_b2·s_w + s_b

__global__ void prep_kernel(const float* __restrict__ f_w1, const float* __restrict__ f_b1,
                            const float* __restrict__ f_w2, const float* __restrict__ f_b2,
                            const float* __restrict__ s_w,  const float* __restrict__ s_b,
                            const float* __restrict__ r_w1, const float* __restrict__ r_b1)
{
    int i = blockIdx.x * blockDim.x + threadIdx.x;
    if (i < 2048) {
        int fid = i >> 5, lane = i & 31;
        int nt = fid >> 3, kt = fid & 7;
        int n = nt * 8 + (lane >> 2);
        int tq = lane & 3;
        int k0 = kt * 16 + 2 * tq;
        float v[4];
        #pragma unroll
        for (int e = 0; e < 4; e++) {
            int k = k0 + (e >> 1) * 8 + (e & 1);
            float s = 0.0f;
            #pragma unroll 8
            for (int t = 0; t < 64; t++) s += f_w2[k * 64 + t] * r_w1[t * 64 + n];
            v[e] = s;
        }
        int ntp = nt >> 1;
        int base = ((ntp * 8 + kt) * 32 + lane) * 4 + (nt & 1) * 2;
        g_Bq[base + 0] = packh(v[0], v[1]);
        g_Bq[base + 1] = packh(v[2], v[3]);
    } else if (i < 2304) {
        // layer-1 B fragments
        int ii = i - 2048;
        int j = ii >> 5, lane = ii & 31;
        int tq = lane & 3;
        u32 r[4];
        #pragma unroll
        for (int half = 0; half < 2; half++) {
            int nt = 2 * j + half;
            int n = nt * 8 + (lane >> 2);
            float wx = f_w1[0 * 128 + n], wy = f_w1[1 * 128 + n], wz = f_w1[2 * 128 + n];
            float bb = f_b1[n];
            float2 hxy = unpackh(packh(wx, wy));
            float2 hzb = unpackh(packh(wz, bb));
            float lwx = wx - hxy.x, lwy = wy - hxy.y;
            float lwz = wz - hzb.x, lbb = bb - hzb.y;
            u32 b0, b1;
            if (tq == 0)      { b0 = packh(wx, wy);  b1 = packh(lwx, lwy); }
            else if (tq == 1) { b0 = packh(wz, bb);  b1 = packh(lwz, 0.0f); }
            else if (tq == 2) { b0 = packh(wx, wy);  b1 = 0u; }
            else              { b0 = packh(wz, lbb); b1 = 0u; }
            r[2 * half] = b0; r[2 * half + 1] = b1;
        }
        g_B1q[j * 32 + lane] = make_uint4(r[0], r[1], r[2], r[3]);
    } else if (i < 2560) {
        // sigma B fragments (n8 tile, col 0 = ws)
        int ii = i - 2304;
        int kt = ii >> 5, lane = ii & 31;
        int n = lane >> 2, tq = lane & 3;
        uint2 o = make_uint2(0u, 0u);
        if (n == 0) {
            int k0 = kt * 16 + 2 * tq;
            float w[4];
            #pragma unroll
            for (int e = 0; e < 4; e++) {
                int k = k0 + (e >> 1) * 8 + (e & 1);
                float s = 0.0f;
                #pragma unroll 8
                for (int t = 0; t < 64; t++) s += f_w2[k * 64 + t] * s_w[t];
                w[e] = s;
            }
            o.x = packh(w[0], w[1]);
            o.y = packh(w[2], w[3]);
        }
        g_WsF[kt * 32 + lane] = o;
    } else if (i < 2624) {
        int j = i - 2560;
        float s = r_b1[j];
        #pragma unroll 8
        for (int t = 0; t < 64; t++) s += f_b2[t] * r_w1[t * 64 + j];
        g_hconst[j] = s;
    } else if (i == 2624) {
        float s = s_b[0];
        for (int t = 0; t < 64; t++) s += f_b2[t] * s_w[t];
        g_sconst[0] = s;
    }
}

// ---------------- dynamic shared layout (bytes) ----------------
#define SM_BQ    0        // 16KB layer-2 B
#define SM_B1    16384    // 4KB layer-1 B
#define SM_WSF   20480    // 2KB sigma B frags (uint2[256])
#define SM_RW2   22528    // [64][4] 1KB
#define SM_SIGB  23552    // sigma_pre[256] 1KB
#define SM_RGBB  24576    // rgbRaw[256] float4 4KB
#define SM_POS   28672    // positions[256] float4 4KB
#define SM_MISC  32768    // [0..2]=r_b2, [3]=sconst
#define SMEM_BYTES 32784

__device__ __forceinline__ float tmap(float u) {
    return (u < 0.5f) ? 2.0f * u : 1.0f / (2.0f - 2.0f * u);
}

#define USTEP ((257.0f / 258.0f) / 256.0f)

__device__ __forceinline__ void ray_pos(int s, float ox, float oy, float oz,
                                        float dx, float dy, float dz,
                                        float& px, float& py, float& pz) {
    float tv = tmap((float)s * USTEP);
    px = ox + dx * tv; py = oy + dy * tv; pz = oz + dz * tv;
    float nrm = sqrtf(px * px + py * py + pz * pz);
    float cs = (nrm <= 1.0f) ? 0.5f : (2.0f - 1.0f / nrm) / nrm * 0.5f;
    px *= cs; py *= cs; pz *= cs;
}

__device__ __forceinline__ float sample_grid(const float* __restrict__ grid,
                                             float px, float py, float pz) {
    float ixf = ((px + 1.0f) * 128.0f - 1.0f) * 0.5f;
    float iyf = ((py + 1.0f) * 128.0f - 1.0f) * 0.5f;
    float izf = ((pz + 1.0f) * 128.0f - 1.0f) * 0.5f;
    float fx0 = floorf(ixf), fy0 = floorf(iyf), fz0 = floorf(izf);
    int ix0 = (int)fx0, iy0 = (int)fy0, iz0 = (int)fz0;
    float fx = ixf - fx0, fy = iyf - fy0, fz = izf - fz0;
    float occ = 0.0f;
    #pragma unroll
    for (int dzc = 0; dzc < 2; dzc++) {
        int cz = iz0 + dzc;
        if (cz < 0 || cz >= 128) continue;
        float wz = dzc ? fz : 1.0f - fz;
        #pragma unroll
        for (int dyc = 0; dyc < 2; dyc++) {
            int cy = iy0 + dyc;
            if (cy < 0 || cy >= 128) continue;
            float wy = dyc ? fy : 1.0f - fy;
            #pragma unroll
            for (int dxc = 0; dxc < 2; dxc++) {
                int cx = ix0 + dxc;
                if (cx < 0 || cx >= 128) continue;
                float wx = dxc ? fx : 1.0f - fx;
                occ += wz * wy * wx * __ldg(&grid[(cz << 14) + (cy << 7) + cx]);
            }
        }
    }
    return occ;
}

// Layer-1 A fragments for one row (contracted position P).
__device__ __forceinline__ void build_a1(float4 P, int tq, u32& aL, u32& aH) {
    u32 c0 = packh(P.x, P.y);
    u32 c1 = packh(P.z, 1.0f);
    float2 fxy = unpackh(c0);
    float2 fz1 = unpackh(c1);
    u32 c2 = packh(P.x - fxy.x, P.y - fxy.y);
    u32 c3 = packh(P.z - fz1.x, 1.0f);
    aL = (tq < 2) ? ((tq == 1) ? c1 : c0) : ((tq == 3) ? c3 : c2);
    aH = (tq == 0) ? c0 : ((tq == 1) ? (c1 & 0xFFFFu) : 0u);
}

__global__ void __launch_bounds__(128, 4) nerf_render_kernel(
    const float* __restrict__ rays_o, const float* __restrict__ rays_d,
    const float* __restrict__ grid,
    const float* __restrict__ r_w1, const float* __restrict__ r_w2,
    const float* __restrict__ r_b2,
    float* __restrict__ out)
{
    extern __shared__ __align__(16) char smdyn[];
    __shared__ float wsumA[4], wsumB[4];
    __shared__ float wred[4][3];

    const int tid = threadIdx.x;
    const int wid = tid >> 5;
    const int lid = tid & 31;
    const int g   = lid >> 2;
    const int tq  = lid & 3;
    const int ray = blockIdx.x;

    const float ox = __ldg(&rays_o[ray * 3 + 0]);
    const float oy = __ldg(&rays_o[ray * 3 + 1]);
    const float oz = __ldg(&rays_o[ray * 3 + 2]);
    const float dx = __ldg(&rays_d[ray * 3 + 0]);
    const float dy = __ldg(&rays_d[ray * 3 + 1]);
    const float dz = __ldg(&rays_d[ray * 3 + 2]);

    float4* posb = (float4*)(smdyn + SM_POS);

    // ---- EARLY: positions + occupancy masks ----
    bool mA, mB;
    {
        float pxA, pyA, pzA, pxB, pyB, pzB;
        ray_pos(tid, ox, oy, oz, dx, dy, dz, pxA, pyA, pzA);
        ray_pos(tid + 128, ox, oy, oz, dx, dy, dz, pxB, pyB, pzB);
        posb[tid]       = make_float4(pxA, pyA, pzA, 0.0f);
        posb[tid + 128] = make_float4(pxB, pyB, pzB, 0.0f);
        mA = sample_grid(grid, pxA, pyA, pzA) > OPACITY_TH;
        mB = sample_grid(grid, pxB, pyB, pzB) > OPACITY_TH;
    }

    // ---- staging ----
    {
        uint4* dstB = (uint4*)(smdyn + SM_BQ);
        const uint4* srcB = (const uint4*)g_Bq;
        #pragma unroll
        for (int i = 0; i < 8; i++) dstB[tid + 128 * i] = srcB[tid + 128 * i];
        uint4* dstB1 = (uint4*)(smdyn + SM_B1);
        #pragma unroll
        for (int i = 0; i < 2; i++) dstB1[tid + 128 * i] = g_B1q[tid + 128 * i];
        uint2* dstWs = (uint2*)(smdyn + SM_WSF);
        #pragma unroll
        for (int i = 0; i < 2; i++) dstWs[tid + 128 * i] = g_WsF[tid + 128 * i];
        if (tid < 64) {
            float hcv = g_hconst[tid]
                      + dx * r_w1[64 * 64 + tid]
                      + dy * r_w1[65 * 64 + tid]
                      + dz * r_w1[66 * 64 + tid];
            *(float4*)(smdyn + SM_RW2 + tid * 16) =
                make_float4(r_w2[tid * 3], r_w2[tid * 3 + 1], r_w2[tid * 3 + 2], hcv);
        }
        if (tid < 3)  ((float*)(smdyn + SM_MISC))[tid] = r_b2[tid];
        if (tid == 3) ((float*)(smdyn + SM_MISC))[3] = g_sconst[0];
    }
    __syncthreads();

    const uint4*  bp   = (const uint4*)(smdyn + SM_BQ);
    const uint4*  b1p  = (const uint4*)(smdyn + SM_B1);
    const uint2*  wsp  = (const uint2*)(smdyn + SM_WSF);
    const float4* qrw2 = (const float4*)(smdyn + SM_RW2);
    float*        sigb = (float*)(smdyn + SM_SIGB);
    float4*       rgbb = (float4*)(smdyn + SM_RGBB);
    const float4* posv = (const float4*)(smdyn + SM_POS);
    const float rb0  = ((const float*)(smdyn + SM_MISC))[0];
    const float rb1  = ((const float*)(smdyn + SM_MISC))[1];
    const float rb2v = ((const float*)(smdyn + SM_MISC))[2];
    const float sconst = ((const float*)(smdyn + SM_MISC))[3];

    // ========== PHASE A: layer-1 MMA -> sigma MMA + layer-2 MMA ==============
    #pragma unroll
    for (int mtp = 0; mtp < 2; mtp++) {
        const int tt0 = wid * 4 + 2 * mtp;
        const int r0 = 16 * tt0 + g;
        const int r1 = r0 + 8;
        const int r2 = r0 + 16;
        const int r3 = r0 + 24;

        u32 aL0, aH0, aL1, aH1, aL2, aH2, aL3, aH3;
        build_a1(posv[r0], tq, aL0, aH0);
        build_a1(posv[r1], tq, aL1, aH1);
        build_a1(posv[r2], tq, aL2, aH2);
        build_a1(posv[r3], tq, aL3, aH3);

        // layer-1 MMAs -> relu -> pack layer-2 A frags
        u32 af0[8][4], af1[8][4];
        #pragma unroll
        for (int j = 0; j < 8; j++) {
            uint4 b = b1p[j * 32 + lid];
            float e0 = 0.0f, e1 = 0.0f, e2 = 0.0f, e3 = 0.0f;
            float f0 = 0.0f, f1 = 0.0f, f2 = 0.0f, f3 = 0.0f;
            float q0 = 0.0f, q1 = 0.0f, q2 = 0.0f, q3 = 0.0f;
            float s0 = 0.0f, s1 = 0.0f, s2 = 0.0f, s3 = 0.0f;
            mma_f16(e0, e1, e2, e3, aL0, aL1, aH0, aH1, b.x, b.y);
            mma_f16(f0, f1, f2, f3, aL0, aL1, aH0, aH1, b.z, b.w);
            mma_f16(q0, q1, q2, q3, aL2, aL3, aH2, aH3, b.x, b.y);
            mma_f16(s0, s1, s2, s3, aL2, aL3, aH2, aH3, b.z, b.w);
            af0[j][0] = packh(fmaxf(e0, 0.0f), fmaxf(e1, 0.0f));
            af0[j][1] = packh(fmaxf(e2, 0.0f), fmaxf(e3, 0.0f));
            af0[j][2] = packh(fmaxf(f0, 0.0f), fmaxf(f1, 0.0f));
            af0[j][3] = packh(fmaxf(f2, 0.0f), fmaxf(f3, 0.0f));
            af1[j][0] = packh(fmaxf(q0, 0.0f), fmaxf(q1, 0.0f));
            af1[j][1] = packh(fmaxf(q2, 0.0f), fmaxf(q3, 0.0f));
            af1[j][2] = packh(fmaxf(s0, 0.0f), fmaxf(s1, 0.0f));
            af1[j][3] = packh(fmaxf(s2, 0.0f), fmaxf(s3, 0.0f));
        }

        // sigma via n8 MMA (col 0 = ws)
        {
            float s00 = 0.0f, s01 = 0.0f, s02 = 0.0f, s03 = 0.0f;
            float s10 = 0.0f, s11 = 0.0f, s12 = 0.0f, s13 = 0.0f;
            #pragma unroll
            for (int kt = 0; kt < 8; kt++) {
                uint2 bs = wsp[kt * 32 + lid];
                mma_f16(s00, s01, s02, s03, af0[kt][0], af0[kt][1], af0[kt][2], af0[kt][3], bs.x, bs.y);
                mma_f16(s10, s11, s12, s13, af1[kt][0], af1[kt][1], af1[kt][2], af1[kt][3], bs.x, bs.y);
            }
            if (tq == 0) { sigb[r0] = s00; sigb[r1] = s02; sigb[r2] = s10; sigb[r3] = s12; }
        }

        // layer-2: 4 ntile-pairs x 8 kt
        float a00 = 0.0f, a01 = 0.0f, a02 = 0.0f;
        float a10 = 0.0f, a11 = 0.0f, a12 = 0.0f;
        float a20 = 0.0f, a21 = 0.0f, a22 = 0.0f;
        float a30 = 0.0f, a31 = 0.0f, a32 = 0.0f;
        #pragma unroll
        for (int ntp = 0; ntp < 4; ntp++) {
            float e00 = 0.0f, e01 = 0.0f, e02 = 0.0f, e03 = 0.0f;
            float e10 = 0.0f, e11 = 0.0f, e12 = 0.0f, e13 = 0.0f;
            float e20 = 0.0f, e21 = 0.0f, e22 = 0.0f, e23 = 0.0f;
            float e30 = 0.0f, e31 = 0.0f, e32 = 0.0f, e33 = 0.0f;
            const uint4* bnt = bp + ntp * 256 + lid;
            #pragma unroll
            for (int kt = 0; kt < 8; kt++) {
                uint4 b = bnt[kt * 32];
                mma_f16(e00, e01, e02, e03, af0[kt][0], af0[kt][1], af0[kt][2], af0[kt][3], b.x, b.y);
                mma_f16(e10, e11, e12, e13, af0[kt][0], af0[kt][1], af0[kt][2], af0[kt][3], b.z, b.w);
                mma_f16(e20, e21, e22, e23, af1[kt][0], af1[kt][1], af1[kt][2], af1[kt][3], b.x, b.y);
                mma_f16(e30, e31, e32, e33, af1[kt][0], af1[kt][1], af1[kt][2], af1[kt][3], b.z, b.w);
            }
            const int cE = ntp * 16 + 2 * tq;
            const int cO = cE + 8;
            float4 wEa = qrw2[cE], wEb = qrw2[cE + 1];
            float4 wOa = qrw2[cO], wOb = qrw2[cO + 1];
            float h;
            h = fmaxf(e00 + wEa.w, 0.0f); a00 = fmaf(h, wEa.x, a00); a01 = fmaf(h, wEa.y, a01); a02 = fmaf(h, wEa.z, a02);
            h = fmaxf(e01 + wEb.w, 0.0f); a00 = fmaf(h, wEb.x, a00); a01 = fmaf(h, wEb.y, a01); a02 = fmaf(h, wEb.z, a02);
            h = fmaxf(e10 + wOa.w, 0.0f); a00 = fmaf(h, wOa.x, a00); a01 = fmaf(h, wOa.y, a01); a02 = fmaf(h, wOa.z, a02);
            h = fmaxf(e11 + wOb.w, 0.0f); a00 = fmaf(h, wOb.x, a00); a01 = fmaf(h, wOb.y, a01); a02 = fmaf(h, wOb.z, a02);
            h = fmaxf(e02 + wEa.w, 0.0f); a10 = fmaf(h, wEa.x, a10); a11 = fmaf(h, wEa.y, a11); a12 = fmaf(h, wEa.z, a12);
            h = fmaxf(e03 + wEb.w, 0.0f); a10 = fmaf(h, wEb.x, a10); a11 = fmaf(h, wEb.y, a11); a12 = fmaf(h, wEb.z, a12);
            h = fmaxf(e12 + wOa.w, 0.0f); a10 = fmaf(h, wOa.x, a10); a11 = fmaf(h, wOa.y, a11); a12 = fmaf(h, wOa.z, a12);
            h = fmaxf(e13 + wOb.w, 0.0f); a10 = fmaf(h, wOb.x, a10); a11 = fmaf(h, wOb.y, a11); a12 = fmaf(h, wOb.z, a12);
            h = fmaxf(e20 + wEa.w, 0.0f); a20 = fmaf(h, wEa.x, a20); a21 = fmaf(h, wEa.y, a21); a22 = fmaf(h, wEa.z, a22);
            h = fmaxf(e21 + wEb.w, 0.0f); a20 = fmaf(h, wEb.x, a20); a21 = fmaf(h, wEb.y, a21); a22 = fmaf(h, wEb.z, a22);
            h = fmaxf(e30 + wOa.w, 0.0f); a20 = fmaf(h, wOa.x, a20); a21 = fmaf(h, wOa.y, a21); a22 = fmaf(h, wOa.z, a22);
            h = fmaxf(e31 + wOb.w, 0.0f); a20 = fmaf(h, wOb.x, a20); a21 = fmaf(h, wOb.y, a21); a22 = fmaf(h, wOb.z, a22);
            h = fmaxf(e22 + wEa.w, 0.0f); a30 = fmaf(h, wEa.x, a30); a31 = fmaf(h, wEa.y, a31); a32 = fmaf(h, wEa.z, a32);
            h = fmaxf(e23 + wEb.w, 0.0f); a30 = fmaf(h, wEb.x, a30); a31 = fmaf(h, wEb.y, a31); a32 = fmaf(h, wEb.z, a32);
            h = fmaxf(e32 + wOa.w, 0.0f); a30 = fmaf(h, wOa.x, a30); a31 = fmaf(h, wOa.y, a31); a32 = fmaf(h, wOa.z, a32);
            h = fmaxf(e33 + wOb.w, 0.0f); a30 = fmaf(h, wOb.x, a30); a31 = fmaf(h, wOb.y, a31); a32 = fmaf(h, wOb.z, a32);
        }
        #pragma unroll
        for (int d = 1; d <= 2; d <<= 1) {
            a00 += __shfl_xor_sync(0xffffffffu, a00, d);
            a01 += __shfl_xor_sync(0xffffffffu, a01, d);
            a02 += __shfl_xor_sync(0xffffffffu, a02, d);
            a10 += __shfl_xor_sync(0xffffffffu, a10, d);
            a11 += __shfl_xor_sync(0xffffffffu, a11, d);
            a12 += __shfl_xor_sync(0xffffffffu, a12, d);
            a20 += __shfl_xor_sync(0xffffffffu, a20, d);
            a21 += __shfl_xor_sync(0xffffffffu, a21, d);
            a22 += __shfl_xor_sync(0xffffffffu, a22, d);
            a30 += __shfl_xor_sync(0xffffffffu, a30, d);
            a31 += __shfl_xor_sync(0xffffffffu, a31, d);
            a32 += __shfl_xor_sync(0xffffffffu, a32, d);
        }
        if (tq == 0) {
            rgbb[r0] = make_float4(1.0f / (1.0f + expf(-(a00 + rb0))),
                                   1.0f / (1.0f + expf(-(a01 + rb1))),
                                   1.0f / (1.0f + expf(-(a02 + rb2v))), 0.0f);
            rgbb[r1] = make_float4(1.0f / (1.0f + expf(-(a10 + rb0))),
                                   1.0f / (1.0f + expf(-(a11 + rb1))),
                                   1.0f / (1.0f + expf(-(a12 + rb2v))), 0.0f);
            rgbb[r2] = make_float4(1.0f / (1.0f + expf(-(a20 + rb0))),
                                   1.0f / (1.0f + expf(-(a21 + rb1))),
                                   1.0f / (1.0f + expf(-(a22 + rb2v))), 0.0f);
            rgbb[r3] = make_float4(1.0f / (1.0f + expf(-(a30 + rb0))),
                                   1.0f / (1.0f + expf(-(a31 + rb1))),
                                   1.0f / (1.0f + expf(-(a32 + rb2v))), 0.0f);
        }
    }
    __syncthreads();

    // ========== PHASE B: scan + weighted accumulation ========================
    float rgb0, rgb1, rgb2;
    {
        float tA  = tmap((float)tid * USTEP);
        float tA1 = tmap((float)(tid + 1) * USTEP);
        float tB  = tmap((float)(tid + 128) * USTEP);
        float tB1 = tmap((float)(tid + 129) * USTEP);
        float distA = tA1 - tA, distB = tB1 - tB;

        float preA = sigb[tid] + sconst;
        float preB = sigb[tid + 128] + sconst;
        float sigmaA = mA ? ((preA > 20.0f) ? preA : log1pf(expf(preA))) : 0.0f;
        float sigmaB = mB ? ((preB > 20.0f) ? preB : log1pf(expf(preB))) : 0.0f;

        float aA = -sigmaA * distA;
        float aB = -sigmaB * distB;
        float incA = aA, incB = aB;
        #pragma unroll
        for (int off = 1; off < 32; off <<= 1) {
            float yA = __shfl_up_sync(0xffffffffu, incA, off);
            float yB = __shfl_up_sync(0xffffffffu, incB, off);
            if (lid >= off) { incA += yA; incB += yB; }
        }
        if (lid == 31) { wsumA[wid] = incA; wsumB[wid] = incB; }
        __syncthreads();
        float offA = 0.0f, offB = 0.0f, totalA = 0.0f;
        #pragma unroll
        for (int i = 0; i < 4; i++) {
            float vA = wsumA[i];
            totalA += vA;
            if (i < wid) { offA += vA; offB += wsumB[i]; }
        }
        float exclA = offA + incA - aA;
        float exclB = totalA + offB + incB - aB;
        float transA = expf(exclA), transB = expf(exclB);
        float weightA = transA * (1.0f - expf(aA));
        float weightB = transB * (1.0f - expf(aB));
        float wA = (mA && transA > EARLY_TERM) ? weightA : 0.0f;
        float wB = (mB && transB > EARLY_TERM) ? weightB : 0.0f;

        float4 cA = rgbb[tid];
        float4 cB = rgbb[tid + 128];
        rgb0 = wA * cA.x + wB * cB.x;
        rgb1 = wA * cA.y + wB * cB.y;
        rgb2 = wA * cA.z + wB * cB.z;
    }

    // ---- deterministic block reduction ----
    #pragma unroll
    for (int off = 16; off > 0; off >>= 1) {
        rgb0 += __shfl_down_sync(0xffffffffu, rgb0, off);
        rgb1 += __shfl_down_sync(0xffffffffu, rgb1, off);
        rgb2 += __shfl_down_sync(0xffffffffu, rgb2, off);
    }
    if (lid == 0) { wred[wid][0] = rgb0; wred[wid][1] = rgb1; wred[wid][2] = rgb2; }
    __syncthreads();
    if (tid < 3) {
        float s = 0.0f;
        #pragma unroll
        for (int w = 0; w < 4; w++) s += wred[w][tid];
        out[ray * 3 + tid] = s;
    }
}

extern "C" void kernel_launch(void* const* d_in, const int* in_sizes, int n_in,
                              void* d_out, int out_size) {
    const float* rays_o = (const float*)d_in[0];
    const float* rays_d = (const float*)d_in[1];
    const float* grid   = (const float*)d_in[2];
    const float* f_w1   = (const float*)d_in[3];
    const float* f_b1   = (const float*)d_in[4];
    const float* f_w2   = (const float*)d_in[5];
    const float* f_b2   = (const float*)d_in[6];
    const float* s_w    = (const float*)d_in[7];
    const float* s_b    = (const float*)d_in[8];
    const float* r_w1   = (const float*)d_in[9];
    const float* r_b1   = (const float*)d_in[10];
    const float* r_w2   = (const float*)d_in[11];
    const float* r_b2   = (const float*)d_in[12];
    float* out = (float*)d_out;

    const int n_rays = in_sizes[0] / 3;

    prep_kernel<<<(2625 + 255) / 256, 256>>>(f_w1, f_b1, f_w2, f_b2, s_w, s_b, r_w1, r_b1);

    cudaFuncSetAttribute(nerf_render_kernel,
                         cudaFuncAttributeMaxDynamicSharedMemorySize, SMEM_BYTES);
    nerf_render_kernel<<<n_rays, 128, SMEM_BYTES>>>(
        rays_o, rays_d, grid, r_w1, r_w2, r_b2, out);
}

// round 15
// speedup vs baseline: 2.3269x; 1.0622x over previous
#include <cuda_runtime.h>
#include <cuda_fp16.h>
#include <math.h>

typedef unsigned int u32;

#define OPACITY_TH 0.01f
#define EARLY_TERM 1e-4f

// pack two floats to f16x2 in ONE instruction: low16 = f16(lo_f), high16 = f16(hi_f)
__device__ __forceinline__ u32 packh(float lo_f, float hi_f) {
    u32 r; asm("cvt.rn.f16x2.f32 %0, %1, %2;" : "=r"(r) : "f"(hi_f), "f"(lo_f)); return r;
}
__device__ __forceinline__ float2 unpackh(u32 v) {
    __half2 h = *reinterpret_cast<__half2*>(&v);
    return __half22float2(h);
}

__device__ __forceinline__ void mma_f16(float& d0, float& d1, float& d2, float& d3,
                                        u32 a0, u32 a1, u32 a2, u32 a3,
                                        u32 b0, u32 b1) {
    asm volatile("mma.sync.aligned.m16n8k16.row.col.f32.f16.f16.f32 "
        "{%0,%1,%2,%3}, {%4,%5,%6,%7}, {%8,%9}, {%0,%1,%2,%3};"
        : "+f"(d0), "+f"(d1), "+f"(d2), "+f"(d3)
        : "r"(a0), "r"(a1), "r"(a2), "r"(a3), "r"(b0), "r"(b1));
}

// ---------------- precomputed globals (prep kernel output) ----------------
__device__ __align__(16) u32 g_Bq[4096];     // layer-2 B, nt-paired (R12 layout)
__device__ __align__(16) uint4 g_B1q[256];   // layer-1 B (R13 layout)
__device__ __align__(8)  uint2 g_WsF[256];   // sigma B frags: col0=ws, cols1-7=0
__device__ __align__(8)  uint2 g_B3q[128];   // layer-3 B frags: cols0-2 = rw2 r,g,b
__device__ float g_hconst[64];               // f_b2 @ r_w1[:64,:] + r_b1
__device__ float g_sconst[1];                // f_b2·s_w + s_b

__global__ void prep_kernel(const float* __restrict__ f_w1, const float* __restrict__ f_b1,
                            const float* __restrict__ f_w2, const float* __restrict__ f_b2,
                            const float* __restrict__ s_w,  const float* __restrict__ s_b,
                            const float* __restrict__ r_w1, const float* __restrict__ r_b1,
                            const float* __restrict__ r_w2)
{
    int i = blockIdx.x * blockDim.x + threadIdx.x;
    if (i < 2048) {
        int fid = i >> 5, lane = i & 31;
        int nt = fid >> 3, kt = fid & 7;
        int n = nt * 8 + (lane >> 2);
        int tq = lane & 3;
        int k0 = kt * 16 + 2 * tq;
        float v[4];
        #pragma unroll
        for (int e = 0; e < 4; e++) {
            int k = k0 + (e >> 1) * 8 + (e & 1);
            float s = 0.0f;
            #pragma unroll 8
            for (int t = 0; t < 64; t++) s += f_w2[k * 64 + t] * r_w1[t * 64 + n];
            v[e] = s;
        }
        int ntp = nt >> 1;
        int base = ((ntp * 8 + kt) * 32 + lane) * 4 + (nt & 1) * 2;
        g_Bq[base + 0] = packh(v[0], v[1]);
        g_Bq[base + 1] = packh(v[2], v[3]);
    } else if (i < 2304) {
        // layer-1 B fragments
        int ii = i - 2048;
        int j = ii >> 5, lane = ii & 31;
        int tq = lane & 3;
        u32 r[4];
        #pragma unroll
        for (int half = 0; half < 2; half++) {
            int nt = 2 * j + half;
            int n = nt * 8 + (lane >> 2);
            float wx = f_w1[0 * 128 + n], wy = f_w1[1 * 128 + n], wz = f_w1[2 * 128 + n];
            float bb = f_b1[n];
            float2 hxy = unpackh(packh(wx, wy));
            float2 hzb = unpackh(packh(wz, bb));
            float lwx = wx - hxy.x, lwy = wy - hxy.y;
            float lwz = wz - hzb.x, lbb = bb - hzb.y;
            u32 b0, b1;
            if (tq == 0)      { b0 = packh(wx, wy);  b1 = packh(lwx, lwy); }
            else if (tq == 1) { b0 = packh(wz, bb);  b1 = packh(lwz, 0.0f); }
            else if (tq == 2) { b0 = packh(wx, wy);  b1 = 0u; }
            else              { b0 = packh(wz, lbb); b1 = 0u; }
            r[2 * half] = b0; r[2 * half + 1] = b1;
        }
        g_B1q[j * 32 + lane] = make_uint4(r[0], r[1], r[2], r[3]);
    } else if (i < 2560) {
        // sigma B fragments (n8 tile, col 0 = ws)
        int ii = i - 2304;
        int kt = ii >> 5, lane = ii & 31;
        int n = lane >> 2, tq = lane & 3;
        uint2 o = make_uint2(0u, 0u);
        if (n == 0) {
            int k0 = kt * 16 + 2 * tq;
            float w[4];
            #pragma unroll
            for (int e = 0; e < 4; e++) {
                int k = k0 + (e >> 1) * 8 + (e & 1);
                float s = 0.0f;
                #pragma unroll 8
                for (int t = 0; t < 64; t++) s += f_w2[k * 64 + t] * s_w[t];
                w[e] = s;
            }
            o.x = packh(w[0], w[1]);
            o.y = packh(w[2], w[3]);
        }
        g_WsF[kt * 32 + lane] = o;
    } else if (i < 2688) {
        // layer-3 B fragments: cols 0..2 = r_w2 columns (r,g,b)
        int ii = i - 2560;
        int kt3 = ii >> 5, lane = ii & 31;
        int n = lane >> 2, tq = lane & 3;
        uint2 o = make_uint2(0u, 0u);
        if (n < 3) {
            int k0 = kt3 * 16 + 2 * tq;
            o.x = packh(r_w2[k0 * 3 + n],       r_w2[(k0 + 1) * 3 + n]);
            o.y = packh(r_w2[(k0 + 8) * 3 + n], r_w2[(k0 + 9) * 3 + n]);
        }
        g_B3q[kt3 * 32 + lane] = o;
    } else if (i < 2752) {
        int j = i - 2688;
        float s = r_b1[j];
        #pragma unroll 8
        for (int t = 0; t < 64; t++) s += f_b2[t] * r_w1[t * 64 + j];
        g_hconst[j] = s;
    } else if (i == 2752) {
        float s = s_b[0];
        for (int t = 0; t < 64; t++) s += f_b2[t] * s_w[t];
        g_sconst[0] = s;
    }
}

// ---------------- dynamic shared layout (bytes) ----------------
#define SM_BQ    0        // 16KB layer-2 B
#define SM_B1    16384    // 4KB layer-1 B
#define SM_WSF   20480    // 2KB sigma B frags
#define SM_B3    22528    // 1KB layer-3 B frags (uint2[128])
#define SM_HC    23552    // 256B hc[64] (per-ray)
#define SM_SIGB  23808    // sigma_pre[256] 1KB
#define SM_RGBB  24832    // rgbRaw[256] float4 4KB
#define SM_POS   28928    // positions[256] float4 4KB
#define SM_MISC  33024    // [0..2]=r_b2, [3]=sconst
#define SMEM_BYTES 33040

__device__ __forceinline__ float tmap(float u) {
    return (u < 0.5f) ? 2.0f * u : 1.0f / (2.0f - 2.0f * u);
}

#define USTEP ((257.0f / 258.0f) / 256.0f)

__device__ __forceinline__ void ray_pos(int s, float ox, float oy, float oz,
                                        float dx, float dy, float dz,
                                        float& px, float& py, float& pz) {
    float tv = tmap((float)s * USTEP);
    px = ox + dx * tv; py = oy + dy * tv; pz = oz + dz * tv;
    float nrm = sqrtf(px * px + py * py + pz * pz);
    float cs = (nrm <= 1.0f) ? 0.5f : (2.0f - 1.0f / nrm) / nrm * 0.5f;
    px *= cs; py *= cs; pz *= cs;
}

__device__ __forceinline__ float sample_grid(const float* __restrict__ grid,
                                             float px, float py, float pz) {
    float ixf = ((px + 1.0f) * 128.0f - 1.0f) * 0.5f;
    float iyf = ((py + 1.0f) * 128.0f - 1.0f) * 0.5f;
    float izf = ((pz + 1.0f) * 128.0f - 1.0f) * 0.5f;
    float fx0 = floorf(ixf), fy0 = floorf(iyf), fz0 = floorf(izf);
    int ix0 = (int)fx0, iy0 = (int)fy0, iz0 = (int)fz0;
    float fx = ixf - fx0, fy = iyf - fy0, fz = izf - fz0;
    float occ = 0.0f;
    #pragma unroll
    for (int dzc = 0; dzc < 2; dzc++) {
        int cz = iz0 + dzc;
        if (cz < 0 || cz >= 128) continue;
        float wz = dzc ? fz : 1.0f - fz;
        #pragma unroll
        for (int dyc = 0; dyc < 2; dyc++) {
            int cy = iy0 + dyc;
            if (cy < 0 || cy >= 128) continue;
            float wy = dyc ? fy : 1.0f - fy;
            #pragma unroll
            for (int dxc = 0; dxc < 2; dxc++) {
                int cx = ix0 + dxc;
                if (cx < 0 || cx >= 128) continue;
                float wx = dxc ? fx : 1.0f - fx;
                occ += wz * wy * wx * __ldg(&grid[(cz << 14) + (cy << 7) + cx]);
            }
        }
    }
    return occ;
}

// Layer-1 A fragments for one row (contracted position P).
__device__ __forceinline__ void build_a1(float4 P, int tq, u32& aL, u32& aH) {
    u32 c0 = packh(P.x, P.y);
    u32 c1 = packh(P.z, 1.0f);
    float2 fxy = unpackh(c0);
    float2 fz1 = unpackh(c1);
    u32 c2 = packh(P.x - fxy.x, P.y - fxy.y);
    u32 c3 = packh(P.z - fz1.x, 1.0f);
    aL = (tq < 2) ? ((tq == 1) ? c1 : c0) : ((tq == 3) ? c3 : c2);
    aH = (tq == 0) ? c0 : ((tq == 1) ? (c1 & 0xFFFFu) : 0u);
}

__global__ void __launch_bounds__(128, 4) nerf_render_kernel(
    const float* __restrict__ rays_o, const float* __restrict__ rays_d,
    const float* __restrict__ grid,
    const float* __restrict__ r_w1,
    const float* __restrict__ r_b2,
    float* __restrict__ out)
{
    extern __shared__ __align__(16) char smdyn[];
    __shared__ float wsumA[4], wsumB[4];
    __shared__ float wred[4][3];

    const int tid = threadIdx.x;
    const int wid = tid >> 5;
    const int lid = tid & 31;
    const int g   = lid >> 2;
    const int tq  = lid & 3;
    const int ray = blockIdx.x;

    const float ox = __ldg(&rays_o[ray * 3 + 0]);
    const float oy = __ldg(&rays_o[ray * 3 + 1]);
    const float oz = __ldg(&rays_o[ray * 3 + 2]);
    const float dx = __ldg(&rays_d[ray * 3 + 0]);
    const float dy = __ldg(&rays_d[ray * 3 + 1]);
    const float dz = __ldg(&rays_d[ray * 3 + 2]);

    float4* posb = (float4*)(smdyn + SM_POS);

    // ---- EARLY: positions + occupancy masks ----
    bool mA, mB;
    {
        float pxA, pyA, pzA, pxB, pyB, pzB;
        ray_pos(tid, ox, oy, oz, dx, dy, dz, pxA, pyA, pzA);
        ray_pos(tid + 128, ox, oy, oz, dx, dy, dz, pxB, pyB, pzB);
        posb[tid]       = make_float4(pxA, pyA, pzA, 0.0f);
        posb[tid + 128] = make_float4(pxB, pyB, pzB, 0.0f);
        mA = sample_grid(grid, pxA, pyA, pzA) > OPACITY_TH;
        mB = sample_grid(grid, pxB, pyB, pzB) > OPACITY_TH;
    }

    // ---- staging ----
    {
        uint4* dstB = (uint4*)(smdyn + SM_BQ);
        const uint4* srcB = (const uint4*)g_Bq;
        #pragma unroll
        for (int i = 0; i < 8; i++) dstB[tid + 128 * i] = srcB[tid + 128 * i];
        uint4* dstB1 = (uint4*)(smdyn + SM_B1);
        #pragma unroll
        for (int i = 0; i < 2; i++) dstB1[tid + 128 * i] = g_B1q[tid + 128 * i];
        uint2* dstWs = (uint2*)(smdyn + SM_WSF);
        #pragma unroll
        for (int i = 0; i < 2; i++) dstWs[tid + 128 * i] = g_WsF[tid + 128 * i];
        ((uint2*)(smdyn + SM_B3))[tid] = g_B3q[tid];
        if (tid < 64) {
            ((float*)(smdyn + SM_HC))[tid] = g_hconst[tid]
                      + dx * r_w1[64 * 64 + tid]
                      + dy * r_w1[65 * 64 + tid]
                      + dz * r_w1[66 * 64 + tid];
        }
        if (tid < 3)  ((float*)(smdyn + SM_MISC))[tid] = r_b2[tid];
        if (tid == 3) ((float*)(smdyn + SM_MISC))[3] = g_sconst[0];
    }
    __syncthreads();

    const uint4*  bp   = (const uint4*)(smdyn + SM_BQ);
    const uint4*  b1p  = (const uint4*)(smdyn + SM_B1);
    const uint2*  wsp  = (const uint2*)(smdyn + SM_WSF);
    const uint2*  b3p  = (const uint2*)(smdyn + SM_B3);
    const float*  hcp  = (const float*)(smdyn + SM_HC);
    float*        sigb = (float*)(smdyn + SM_SIGB);
    float*        rgbf = (float*)(smdyn + SM_RGBB);   // float4 stride 4
    float4*       rgbb = (float4*)(smdyn + SM_RGBB);
    const float4* posv = (const float4*)(smdyn + SM_POS);
    const float rb0  = ((const float*)(smdyn + SM_MISC))[0];
    const float rb1  = ((const float*)(smdyn + SM_MISC))[1];
    const float rb2v = ((const float*)(smdyn + SM_MISC))[2];
    const float sconst = ((const float*)(smdyn + SM_MISC))[3];

    // ========== PHASE A: layer-1 MMA -> sigma MMA + layer-2 MMA -> layer-3 MMA
    #pragma unroll
    for (int mtp = 0; mtp < 2; mtp++) {
        const int tt0 = wid * 4 + 2 * mtp;
        const int r0 = 16 * tt0 + g;
        const int r1 = r0 + 8;
        const int r2 = r0 + 16;
        const int r3 = r0 + 24;

        u32 aL0, aH0, aL1, aH1, aL2, aH2, aL3, aH3;
        build_a1(posv[r0], tq, aL0, aH0);
        build_a1(posv[r1], tq, aL1, aH1);
        build_a1(posv[r2], tq, aL2, aH2);
        build_a1(posv[r3], tq, aL3, aH3);

        // layer-1 MMAs -> relu -> pack layer-2 A frags
        u32 af0[8][4], af1[8][4];
        #pragma unroll
        for (int j = 0; j < 8; j++) {
            uint4 b = b1p[j * 32 + lid];
            float e0 = 0.0f, e1 = 0.0f, e2 = 0.0f, e3 = 0.0f;
            float f0 = 0.0f, f1 = 0.0f, f2 = 0.0f, f3 = 0.0f;
            float q0 = 0.0f, q1 = 0.0f, q2 = 0.0f, q3 = 0.0f;
            float s0 = 0.0f, s1 = 0.0f, s2 = 0.0f, s3 = 0.0f;
            mma_f16(e0, e1, e2, e3, aL0, aL1, aH0, aH1, b.x, b.y);
            mma_f16(f0, f1, f2, f3, aL0, aL1, aH0, aH1, b.z, b.w);
            mma_f16(q0, q1, q2, q3, aL2, aL3, aH2, aH3, b.x, b.y);
            mma_f16(s0, s1, s2, s3, aL2, aL3, aH2, aH3, b.z, b.w);
            af0[j][0] = packh(fmaxf(e0, 0.0f), fmaxf(e1, 0.0f));
            af0[j][1] = packh(fmaxf(e2, 0.0f), fmaxf(e3, 0.0f));
            af0[j][2] = packh(fmaxf(f0, 0.0f), fmaxf(f1, 0.0f));
            af0[j][3] = packh(fmaxf(f2, 0.0f), fmaxf(f3, 0.0f));
            af1[j][0] = packh(fmaxf(q0, 0.0f), fmaxf(q1, 0.0f));
            af1[j][1] = packh(fmaxf(q2, 0.0f), fmaxf(q3, 0.0f));
            af1[j][2] = packh(fmaxf(s0, 0.0f), fmaxf(s1, 0.0f));
            af1[j][3] = packh(fmaxf(s2, 0.0f), fmaxf(s3, 0.0f));
        }

        // sigma via n8 MMA (col 0 = ws)
        {
            float s00 = 0.0f, s01 = 0.0f, s02 = 0.0f, s03 = 0.0f;
            float s10 = 0.0f, s11 = 0.0f, s12 = 0.0f, s13 = 0.0f;
            #pragma unroll
            for (int kt = 0; kt < 8; kt++) {
                uint2 bs = wsp[kt * 32 + lid];
                mma_f16(s00, s01, s02, s03, af0[kt][0], af0[kt][1], af0[kt][2], af0[kt][3], bs.x, bs.y);
                mma_f16(s10, s11, s12, s13, af1[kt][0], af1[kt][1], af1[kt][2], af1[kt][3], bs.x, bs.y);
            }
            if (tq == 0) { sigb[r0] = s00; sigb[r1] = s02; sigb[r2] = s10; sigb[r3] = s12; }
        }

        // layer-2 MMAs -> +hc, relu, pack layer-3 A frags -> layer-3 MMA
        float c00 = 0.0f, c01 = 0.0f, c02 = 0.0f, c03 = 0.0f;   // tile0 rgb accum
        float c10 = 0.0f, c11 = 0.0f, c12 = 0.0f, c13 = 0.0f;   // tile1 rgb accum
        #pragma unroll
        for (int ntp = 0; ntp < 4; ntp++) {
            float e00 = 0.0f, e01 = 0.0f, e02 = 0.0f, e03 = 0.0f;
            float e10 = 0.0f, e11 = 0.0f, e12 = 0.0f, e13 = 0.0f;
            float e20 = 0.0f, e21 = 0.0f, e22 = 0.0f, e23 = 0.0f;
            float e30 = 0.0f, e31 = 0.0f, e32 = 0.0f, e33 = 0.0f;
            const uint4* bnt = bp + ntp * 256 + lid;
            #pragma unroll
            for (int kt = 0; kt < 8; kt++) {
                uint4 b = bnt[kt * 32];
                mma_f16(e00, e01, e02, e03, af0[kt][0], af0[kt][1], af0[kt][2], af0[kt][3], b.x, b.y);
                mma_f16(e10, e11, e12, e13, af0[kt][0], af0[kt][1], af0[kt][2], af0[kt][3], b.z, b.w);
                mma_f16(e20, e21, e22, e23, af1[kt][0], af1[kt][1], af1[kt][2], af1[kt][3], b.x, b.y);
                mma_f16(e30, e31, e32, e33, af1[kt][0], af1[kt][1], af1[kt][2], af1[kt][3], b.z, b.w);
            }
            const int cE = ntp * 16 + 2 * tq;
            float2 hcE = *(const float2*)&hcp[cE];
            float2 hcO = *(const float2*)&hcp[cE + 8];
            uint2 b3 = b3p[ntp * 32 + lid];
            // tile0 A3 frags
            u32 x0 = packh(fmaxf(e00 + hcE.x, 0.0f), fmaxf(e01 + hcE.y, 0.0f));
            u32 x1 = packh(fmaxf(e02 + hcE.x, 0.0f), fmaxf(e03 + hcE.y, 0.0f));
            u32 x2 = packh(fmaxf(e10 + hcO.x, 0.0f), fmaxf(e11 + hcO.y, 0.0f));
            u32 x3 = packh(fmaxf(e12 + hcO.x, 0.0f), fmaxf(e13 + hcO.y, 0.0f));
            mma_f16(c00, c01, c02, c03, x0, x1, x2, x3, b3.x, b3.y);
            // tile1 A3 frags
            u32 y0 = packh(fmaxf(e20 + hcE.x, 0.0f), fmaxf(e21 + hcE.y, 0.0f));
            u32 y1 = packh(fmaxf(e22 + hcE.x, 0.0f), fmaxf(e23 + hcE.y, 0.0f));
            u32 y2 = packh(fmaxf(e30 + hcO.x, 0.0f), fmaxf(e31 + hcO.y, 0.0f));
            u32 y3 = packh(fmaxf(e32 + hcO.x, 0.0f), fmaxf(e33 + hcO.y, 0.0f));
            mma_f16(c10, c11, c12, c13, y0, y1, y2, y3, b3.x, b3.y);
        }
        // write weight-independent colors: tq0 holds (r,g), tq1 holds b
        if (tq == 0) {
            *(float2*)&rgbf[r0 * 4] = make_float2(1.0f / (1.0f + expf(-(c00 + rb0))),
                                                  1.0f / (1.0f + expf(-(c01 + rb1))));
            *(float2*)&rgbf[r1 * 4] = make_float2(1.0f / (1.0f + expf(-(c02 + rb0))),
                                                  1.0f / (1.0f + expf(-(c03 + rb1))));
            *(float2*)&rgbf[r2 * 4] = make_float2(1.0f / (1.0f + expf(-(c10 + rb0))),
                                                  1.0f / (1.0f + expf(-(c11 + rb1))));
            *(float2*)&rgbf[r3 * 4] = make_float2(1.0f / (1.0f + expf(-(c12 + rb0))),
                                                  1.0f / (1.0f + expf(-(c13 + rb1))));
        } else if (tq == 1) {
            rgbf[r0 * 4 + 2] = 1.0f / (1.0f + expf(-(c00 + rb2v)));
            rgbf[r1 * 4 + 2] = 1.0f / (1.0f + expf(-(c02 + rb2v)));
            rgbf[r2 * 4 + 2] = 1.0f / (1.0f + expf(-(c10 + rb2v)));
            rgbf[r3 * 4 + 2] = 1.0f / (1.0f + expf(-(c12 + rb2v)));
        }
    }
    __syncthreads();

    // ========== PHASE B: scan + weighted accumulation ========================
    float rgb0, rgb1, rgb2;
    {
        float tA  = tmap((float)tid * USTEP);
        float tA1 = tmap((float)(tid + 1) * USTEP);
        float tB  = tmap((float)(tid + 128) * USTEP);
        float tB1 = tmap((float)(tid + 129) * USTEP);
        float distA = tA1 - tA, distB = tB1 - tB;

        float preA = sigb[tid] + sconst;
        float preB = sigb[tid + 128] + sconst;
        float sigmaA = mA ? ((preA > 20.0f) ? preA : log1pf(expf(preA))) : 0.0f;
        float sigmaB = mB ? ((preB > 20.0f) ? preB : log1pf(expf(preB))) : 0.0f;

        float aA = -sigmaA * distA;
        float aB = -sigmaB * distB;
        float incA = aA, incB = aB;
        #pragma unroll
        for (int off = 1; off < 32; off <<= 1) {
            float yA = __shfl_up_sync(0xffffffffu, incA, off);
            float yB = __shfl_up_sync(0xffffffffu, incB, off);
            if (lid >= off) { incA += yA; incB += yB; }
        }
        if (lid == 31) { wsumA[wid] = incA; wsumB[wid] = incB; }
        __syncthreads();
        float offA = 0.0f, offB = 0.0f, totalA = 0.0f;
        #pragma unroll
        for (int i = 0; i < 4; i++) {
            float vA = wsumA[i];
            totalA += vA;
            if (i < wid) { offA += vA; offB += wsumB[i]; }
        }
        float exclA = offA + incA - aA;
        float exclB = totalA + offB + incB - aB;
        float transA = expf(exclA), transB = expf(exclB);
        float weightA = transA * (1.0f - expf(aA));
        float weightB = transB * (1.0f - expf(aB));
        float wA = (mA && transA > EARLY_TERM) ? weightA : 0.0f;
        float wB = (mB && transB > EARLY_TERM) ? weightB : 0.0f;

        float4 cA = rgbb[tid];
        float4 cB = rgbb[tid + 128];
        rgb0 = wA * cA.x + wB * cB.x;
        rgb1 = wA * cA.y + wB * cB.y;
        rgb2 = wA * cA.z + wB * cB.z;
    }

    // ---- deterministic block reduction ----
    #pragma unroll
    for (int off = 16; off > 0; off >>= 1) {
        rgb0 += __shfl_down_sync(0xffffffffu, rgb0, off);
        rgb1 += __shfl_down_sync(0xffffffffu, rgb1, off);
        rgb2 += __shfl_down_sync(0xffffffffu, rgb2, off);
    }
    if (lid == 0) { wred[wid][0] = rgb0; wred[wid][1] = rgb1; wred[wid][2] = rgb2; }
    __syncthreads();
    if (tid < 3) {
        float s = 0.0f;
        #pragma unroll
        for (int w = 0; w < 4; w++) s += wred[w][tid];
        out[ray * 3 + tid] = s;
    }
}

extern "C" void kernel_launch(void* const* d_in, const int* in_sizes, int n_in,
                              void* d_out, int out_size) {
    const float* rays_o = (const float*)d_in[0];
    const float* rays_d = (const float*)d_in[1];
    const float* grid   = (const float*)d_in[2];
    const float* f_w1   = (const float*)d_in[3];
    const float* f_b1   = (const float*)d_in[4];
    const float* f_w2   = (const float*)d_in[5];
    const float* f_b2   = (const float*)d_in[6];
    const float* s_w    = (const float*)d_in[7];
    const float* s_b    = (const float*)d_in[8];
    const float* r_w1   = (const float*)d_in[9];
    const float* r_b1   = (const float*)d_in[10];
    const float* r_w2   = (const float*)d_in[11];
    const float* r_b2   = (const float*)d_in[12];
    float* out = (float*)d_out;

    const int n_rays = in_sizes[0] / 3;

    prep_kernel<<<(2753 + 255) / 256, 256>>>(f_w1, f_b1, f_w2, f_b2, s_w, s_b, r_w1, r_b1, r_w2);

    cudaFuncSetAttribute(nerf_render_kernel,
                         cudaFuncAttributeMaxDynamicSharedMemorySize, SMEM_BYTES);
    nerf_render_kernel<<<n_rays, 128, SMEM_BYTES>>>(
        rays_o, rays_d, grid, r_w1, r_b2, out);
}